// round 1
// baseline (speedup 1.0000x reference)
#include <cuda_runtime.h>

#define BB_ 64
#define LL_ 2048
#define HH_ 128
#define DW_ 128

// Ping-pong buffers for the tree levels (allocation-free scratch).
__device__ float g_bufA[BB_ * LL_ * HH_];        // 67 MB
__device__ float g_bufB[BB_ * (LL_ / 2) * HH_];  // 33.5 MB

extern __shared__ float smem[];

// ---------------- packed f32x2 helpers (sm_103a FFMA2) ----------------
__device__ __forceinline__ unsigned long long pk2(float lo, float hi) {
    unsigned long long r;
    asm("mov.b64 %0, {%1, %2};" : "=l"(r) : "f"(lo), "f"(hi));
    return r;
}
__device__ __forceinline__ void fma2(unsigned long long& d, unsigned long long a,
                                     unsigned long long b) {
    asm("fma.rn.f32x2 %0, %1, %2, %0;" : "+l"(d) : "l"(a), "l"(b));
}
__device__ __forceinline__ float2 upk2(unsigned long long v) {
    float2 r;
    asm("mov.b64 {%0, %1}, %2;" : "=f"(r.x), "=f"(r.y) : "l"(v));
    return r;
}
__device__ __forceinline__ float sigf(float x) {
    return 1.0f / (1.0f + __expf(-x));
}
__device__ __forceinline__ float tanh_f(float x) {
    // 1 - 2/(e^{2x}+1); saturates correctly at +-1 for large |x|
    return 1.0f - 2.0f / (__expf(2.0f * x) + 1.0f);
}
__device__ __forceinline__ float getc(float4 v, int j) {
    return (j == 0) ? v.x : (j == 1) ? v.y : (j == 2) ? v.z : v.w;
}

// ---------------- Stage 0: h0 = emb[ids] @ W_wh  (M-tile 64, N=128) ----------------
__global__ void embed_gemm(const int* __restrict__ ids,
                           const float* __restrict__ emb,
                           const float* __restrict__ Wwh) {
    float* As = smem;              // 64*128
    float* Ws = smem + 64 * 128;   // 128*128
    float4* As4 = (float4*)As;
    float4* Ws4 = (float4*)Ws;
    const float4* emb4 = (const float4*)emb;
    const float4* W4 = (const float4*)Wwh;

    int t = threadIdx.x;
    int r0 = blockIdx.x * 64;

    for (int i = t; i < 64 * 32; i += 256) {
        int rr = i >> 5, c = i & 31;
        int id = ids[r0 + rr];
        As4[i] = emb4[(long long)id * 32 + c];
    }
    for (int i = t; i < 128 * 32; i += 256) Ws4[i] = W4[i];
    __syncthreads();

    int tx = t & 31, ty = t >> 5;  // tx: 4 cols each, ty: 8 rows each
    unsigned long long acc[8][2];
    unsigned long long z2 = pk2(0.f, 0.f);
#pragma unroll
    for (int m = 0; m < 8; m++) { acc[m][0] = z2; acc[m][1] = z2; }

    for (int k0 = 0; k0 < 128; k0 += 4) {
        float4 a4[8];
#pragma unroll
        for (int m = 0; m < 8; m++) a4[m] = As4[(ty * 8 + m) * 32 + (k0 >> 2)];
#pragma unroll
        for (int kk = 0; kk < 4; kk++) {
            float4 bv = Ws4[(k0 + kk) * 32 + tx];
            unsigned long long blo = pk2(bv.x, bv.y), bhi = pk2(bv.z, bv.w);
#pragma unroll
            for (int m = 0; m < 8; m++) {
                float a = getc(a4[m], kk);
                unsigned long long aa = pk2(a, a);
                fma2(acc[m][0], aa, blo);
                fma2(acc[m][1], aa, bhi);
            }
        }
    }
    float4* out4 = (float4*)g_bufA;
#pragma unroll
    for (int m = 0; m < 8; m++) {
        float2 lo = upk2(acc[m][0]), hi = upk2(acc[m][1]);
        out4[(long long)(r0 + ty * 8 + m) * 32 + tx] = make_float4(lo.x, lo.y, hi.x, hi.y);
    }
}

// ---------------- Tree level: fused (hl+hr)@W_hh (5 gate chunks) + LSTM cell ----------------
// smem: hl(32x128) hr(32x128) x(32x128) W(128x128) s(5x32x128) bias(640)
__global__ void combine_level(int src_sel, float* __restrict__ out_param, int dst_sel,
                              const float* __restrict__ Whh,
                              const float* __restrict__ bhh,
                              int n_half, int rows) {
    float* hl_s = smem;                 // 4096
    float* hr_s = hl_s + 32 * 128;      // 4096
    float* x_s  = hr_s + 32 * 128;      // 4096
    float* Ws   = x_s + 32 * 128;       // 16384
    float* s_s  = Ws + 128 * 128;       // 20480
    float* bb   = s_s + 5 * 32 * 128;   // 640

    const float* hin = (src_sel == 0) ? g_bufA : g_bufB;
    float* hout = (dst_sel == 0) ? g_bufA : (dst_sel == 1) ? g_bufB : out_param;

    int t = threadIdx.x;
    int r0 = blockIdx.x * 32;

    for (int i = t; i < 640; i += 256) bb[i] = 2.0f * bhh[i];

    const float4* hin4 = (const float4*)hin;
    for (int i = t; i < 32 * 32; i += 256) {
        int rr = i >> 5, c = i & 31;
        int r = r0 + rr;
        float4 l4, rr4;
        if (r < rows) {
            int b = r / n_half, ii = r - b * n_half;
            long long base = (long long)b * (2 * n_half);
            l4 = hin4[(base + 2 * ii) * 32 + c];
            rr4 = hin4[(base + 2 * ii + 1) * 32 + c];
        } else {
            l4 = make_float4(0, 0, 0, 0);
            rr4 = l4;
        }
        ((float4*)hl_s)[i] = l4;
        ((float4*)hr_s)[i] = rr4;
        ((float4*)x_s)[i] = make_float4(l4.x + rr4.x, l4.y + rr4.y, l4.z + rr4.z, l4.w + rr4.w);
    }
    __syncthreads();

    int tx = t & 31, ty = t >> 5;  // tx: 4 cols, ty: 4 rows each (M=32)
    const float4* x4p = (const float4*)x_s;
    float4* Ws4 = (float4*)Ws;

    for (int g = 0; g < 5; ++g) {
        __syncthreads();  // everyone done reading previous gate's W
        for (int i = t; i < 4096; i += 256) {
            int k = i >> 5, j4 = i & 31;
            Ws4[i] = *(const float4*)&Whh[(long long)k * 640 + g * 128 + j4 * 4];
        }
        __syncthreads();

        unsigned long long acc[4][2];
        unsigned long long z2 = pk2(0.f, 0.f);
#pragma unroll
        for (int m = 0; m < 4; m++) { acc[m][0] = z2; acc[m][1] = z2; }

        for (int k0 = 0; k0 < 128; k0 += 4) {
            float4 a4[4];
#pragma unroll
            for (int m = 0; m < 4; m++) a4[m] = x4p[(ty * 4 + m) * 32 + (k0 >> 2)];
#pragma unroll
            for (int kk = 0; kk < 4; kk++) {
                float4 bv = Ws4[(k0 + kk) * 32 + tx];
                unsigned long long blo = pk2(bv.x, bv.y), bhi = pk2(bv.z, bv.w);
#pragma unroll
                for (int m = 0; m < 4; m++) {
                    float a = getc(a4[m], kk);
                    unsigned long long aa = pk2(a, a);
                    fma2(acc[m][0], aa, blo);
                    fma2(acc[m][1], aa, bhi);
                }
            }
        }
        float4* s4 = (float4*)(s_s + g * 32 * 128);
#pragma unroll
        for (int m = 0; m < 4; m++) {
            float2 lo = upk2(acc[m][0]), hi = upk2(acc[m][1]);
            s4[(ty * 4 + m) * 32 + tx] = make_float4(lo.x, lo.y, hi.x, hi.y);
        }
    }
    __syncthreads();

    // Epilogue: LSTM cell on this thread's 4 rows x 4 cols
    const float4* s4all = (const float4*)s_s;
    const float4* bb4 = (const float4*)bb;
    float4 bi = bb4[0 * 32 + tx], bl = bb4[1 * 32 + tx], br = bb4[2 * 32 + tx],
           bo = bb4[3 * 32 + tx], bg = bb4[4 * 32 + tx];
#pragma unroll
    for (int m = 0; m < 4; m++) {
        int rr = ty * 4 + m;
        int r = r0 + rr;
        if (r >= rows) continue;
        float4 si = s4all[0 * 1024 + rr * 32 + tx];
        float4 sl = s4all[1 * 1024 + rr * 32 + tx];
        float4 sr = s4all[2 * 1024 + rr * 32 + tx];
        float4 so = s4all[3 * 1024 + rr * 32 + tx];
        float4 sg = s4all[4 * 1024 + rr * 32 + tx];
        float4 l4 = ((const float4*)hl_s)[rr * 32 + tx];
        float4 r4 = ((const float4*)hr_s)[rr * 32 + tx];
        float ov[4];
#pragma unroll
        for (int j = 0; j < 4; j++) {
            float ig = sigf(getc(si, j) + getc(bi, j));
            float lf = sigf(getc(sl, j) + getc(bl, j));
            float rf = sigf(getc(sr, j) + getc(br, j));
            float og = sigf(getc(so, j) + getc(bo, j));
            float gg = tanh_f(getc(sg, j) + getc(bg, j));
            float cc = ig * gg + lf * getc(l4, j) + rf * getc(r4, j);
            ov[j] = og * tanh_f(cc);
        }
        ((float4*)hout)[(long long)r * 32 + tx] = make_float4(ov[0], ov[1], ov[2], ov[3]);
    }
}

// ---------------- launcher ----------------
extern "C" void kernel_launch(void* const* d_in, const int* in_sizes, int n_in,
                              void* d_out, int out_size) {
    const int* ids = (const int*)d_in[0];
    const float* emb = (const float*)d_in[1];
    const float* Wwh = (const float*)d_in[2];
    const float* Whh = (const float*)d_in[3];
    const float* bhh = (const float*)d_in[4];
    float* out = (float*)d_out;

    const int smem_embed = (64 * 128 + 128 * 128) * 4;                       // 96 KB
    const int smem_comb = (3 * 32 * 128 + 128 * 128 + 5 * 32 * 128 + 640) * 4;  // ~194.5 KB
    cudaFuncSetAttribute(embed_gemm, cudaFuncAttributeMaxDynamicSharedMemorySize, smem_embed);
    cudaFuncSetAttribute(combine_level, cudaFuncAttributeMaxDynamicSharedMemorySize, smem_comb);

    // Stage 0: 131072 rows / 64 per block
    embed_gemm<<<(BB_ * LL_) / 64, 256, smem_embed>>>(ids, emb, Wwh);

    // Tree levels t = 1..11, n_half = 2048 >> t
    for (int tlev = 1; tlev <= 11; ++tlev) {
        int n_half = LL_ >> tlev;
        int rows = BB_ * n_half;
        int src_sel = (tlev & 1) ? 0 : 1;                     // odd reads A, even reads B
        int dst_sel = (tlev == 11) ? 2 : ((tlev & 1) ? 1 : 0);  // odd writes B, even writes A
        int blocks = (rows + 31) / 32;
        combine_level<<<blocks, 256, smem_comb>>>(src_sel, out, dst_sel, Whh, bhh,
                                                  n_half, rows);
    }
}

// round 2
// speedup vs baseline: 1.3892x; 1.3892x over previous
#include <cuda_runtime.h>

#define BB_ 64
#define LL_ 2048

// Ping-pong buffers for the tree levels (allocation-free scratch).
__device__ float g_bufA[BB_ * LL_ * 128];        // 67 MB
__device__ float g_bufB[BB_ * (LL_ / 2) * 128];  // 33.5 MB

extern __shared__ float smem[];

typedef unsigned long long ull;

// ---------------- packed f32x2 helpers (sm_103a FFMA2) ----------------
__device__ __forceinline__ ull pk2(float lo, float hi) {
    ull r;
    asm("mov.b64 %0, {%1, %2};" : "=l"(r) : "f"(lo), "f"(hi));
    return r;
}
__device__ __forceinline__ void fma2(ull& d, ull a, ull b) {
    asm("fma.rn.f32x2 %0, %1, %2, %0;" : "+l"(d) : "l"(a), "l"(b));
}
__device__ __forceinline__ float2 upk2(ull v) {
    float2 r;
    asm("mov.b64 {%0, %1}, %2;" : "=f"(r.x), "=f"(r.y) : "l"(v));
    return r;
}
__device__ __forceinline__ float sigf(float x) { return 1.0f / (1.0f + __expf(-x)); }
__device__ __forceinline__ float tanh_f(float x) {
    return 1.0f - 2.0f / (__expf(2.0f * x) + 1.0f);
}

// ---------------- cp.async helpers ----------------
__device__ __forceinline__ void cp16(float* s, const float4* g) {
    unsigned a = (unsigned)__cvta_generic_to_shared(s);
    asm volatile("cp.async.cg.shared.global [%0], [%1], 16;" :: "r"(a), "l"(g));
}
#define CP_COMMIT() asm volatile("cp.async.commit_group;")
#define CP_WAIT1()  asm volatile("cp.async.wait_group 1;")
#define CP_WAIT0()  asm volatile("cp.async.wait_group 0;")

// =====================================================================
// Stage 0: h0 = emb[ids] @ W_wh.  Block: M=64 rows x N=128.  256 thr.
// Thread tile 4 rows x 8 cols. W_wh (64 KB) resident in smem.
// smem: x(64x129) + W(128x128) = 98560 B -> 2 CTAs/SM.
// =====================================================================
__global__ __launch_bounds__(256, 2) void embed_gemm(const int* __restrict__ ids,
                                                     const float* __restrict__ emb,
                                                     const float* __restrict__ Wwh) {
    float* x_s = smem;             // 64*129 floats
    float* w_s = smem + 64 * 129;  // 128*128 floats

    int t = threadIdx.x;
    int r0 = blockIdx.x * 64;

    // Load W (contiguous, row-major [k][128])
    const float4* W4 = (const float4*)Wwh;
    for (int i = t; i < 4096; i += 256) ((float4*)w_s)[i] = W4[i];

    // Gather x rows (pitch 129 to decorrelate banks)
    for (int i = t; i < 64 * 32; i += 256) {
        int rr = i >> 5, c4 = i & 31;
        int id = ids[r0 + rr];
        float4 v = ((const float4*)emb)[(long long)id * 32 + c4];
        float* xp = &x_s[rr * 129 + c4 * 4];
        xp[0] = v.x; xp[1] = v.y; xp[2] = v.z; xp[3] = v.w;
    }
    __syncthreads();

    int lane = t & 31, warp = t >> 5;
    int wy = warp >> 2, wx = warp & 3;      // wy 0-1 (rows), wx 0-3 (cols)
    int rowg = lane >> 2, colg = lane & 3;  // 8 row groups x 4 col groups
    int rbase = wy * 32 + rowg * 4;
    int cbase = wx * 32 + colg * 8;

    ull acc[4][4];
#pragma unroll
    for (int m = 0; m < 4; m++)
#pragma unroll
        for (int j = 0; j < 4; j++) acc[m][j] = 0ULL;

#pragma unroll 4
    for (int k = 0; k < 128; k++) {
        ull ap[4];
#pragma unroll
        for (int m = 0; m < 4; m++) {
            float a = x_s[(rbase + m) * 129 + k];
            ap[m] = pk2(a, a);
        }
        float4 b0 = *(const float4*)&w_s[k * 128 + cbase];
        float4 b1 = *(const float4*)&w_s[k * 128 + cbase + 4];
        ull bl[4] = {pk2(b0.x, b0.y), pk2(b0.z, b0.w), pk2(b1.x, b1.y), pk2(b1.z, b1.w)};
#pragma unroll
        for (int m = 0; m < 4; m++)
#pragma unroll
            for (int j = 0; j < 4; j++) fma2(acc[m][j], ap[m], bl[j]);
    }

#pragma unroll
    for (int m = 0; m < 4; m++) {
        float2 p0 = upk2(acc[m][0]), p1 = upk2(acc[m][1]);
        float2 p2 = upk2(acc[m][2]), p3 = upk2(acc[m][3]);
        long long row = r0 + rbase + m;
        *(float4*)&g_bufA[row * 128 + cbase]     = make_float4(p0.x, p0.y, p1.x, p1.y);
        *(float4*)&g_bufA[row * 128 + cbase + 4] = make_float4(p2.x, p2.y, p3.x, p3.y);
    }
}

// =====================================================================
// Tree level: s = (hl+hr) @ W_hh (128x640) + 2b, fused LSTM epilogue.
// Block: M=32 rows x N=640 (all 5 gates). 256 thr.
// Thread tile 4 rows x 4 cols x 5 gates -> 40 ULL accs, epilogue in regs.
// W streamed in k-slices of 8 via cp.async double buffer.
// smem: x(32x129) + hl(32x132) + hr(32x132) + W(2x8x640) = 91264 B -> 2 CTAs/SM.
// =====================================================================
#define KS 8
#define NSTAGE 16

__global__ __launch_bounds__(256, 2) void combine2(int src_sel, float* __restrict__ out_param,
                                                   int dst_sel,
                                                   const float* __restrict__ Whh,
                                                   const float* __restrict__ bhh,
                                                   int lg_nhalf) {
    float* x_s  = smem;                       // 32*129
    float* hl_s = x_s + 32 * 129;             // 32*132
    float* hr_s = hl_s + 32 * 132;            // 32*132
    float* w_s  = hr_s + 32 * 132;            // 2*8*640

    const float* hin = (src_sel == 0) ? g_bufA : g_bufB;
    float* hout = (dst_sel == 0) ? g_bufA : (dst_sel == 1) ? g_bufB : out_param;

    int t = threadIdx.x;
    int r0 = blockIdx.x * 32;
    int n_half = 1 << lg_nhalf;

    // Kick off W stages 0 and 1 first to overlap with the x gather.
    {
        const float4* g0 = (const float4*)(Whh);
        float* d0 = w_s;
#pragma unroll
        for (int j = 0; j < 5; j++) { int idx = t + j * 256; cp16(d0 + idx * 4, g0 + idx); }
        CP_COMMIT();
        const float4* g1 = (const float4*)(Whh + KS * 640);
        float* d1 = w_s + KS * 640;
#pragma unroll
        for (int j = 0; j < 5; j++) { int idx = t + j * 256; cp16(d1 + idx * 4, g1 + idx); }
        CP_COMMIT();
    }

    // Load hl/hr pairs, build x = hl + hr.
    const float4* hin4 = (const float4*)hin;
    for (int i = t; i < 32 * 32; i += 256) {
        int rr = i >> 5, c4 = i & 31;
        int r = r0 + rr;
        int b = r >> lg_nhalf;
        int ii = r - (b << lg_nhalf);
        long long base = (long long)b * (2 * n_half);
        float4 l4 = hin4[(base + 2 * ii) * 32 + c4];
        float4 r4 = hin4[(base + 2 * ii + 1) * 32 + c4];
        *(float4*)&hl_s[rr * 132 + c4 * 4] = l4;
        *(float4*)&hr_s[rr * 132 + c4 * 4] = r4;
        float* xp = &x_s[rr * 129 + c4 * 4];
        xp[0] = l4.x + r4.x; xp[1] = l4.y + r4.y; xp[2] = l4.z + r4.z; xp[3] = l4.w + r4.w;
    }

    int lane = t & 31, warp = t >> 5;
    int wy = warp >> 2, wx = warp & 3;      // 2 x 4 warps
    int rowg = lane >> 3, colg = lane & 7;  // 4 row groups x 8 col groups
    int rbase = wy * 16 + rowg * 4;
    int cbase = wx * 32 + colg * 4;

    ull acc[4][5][2];
#pragma unroll
    for (int m = 0; m < 4; m++)
#pragma unroll
        for (int g = 0; g < 5; g++) { acc[m][g][0] = 0ULL; acc[m][g][1] = 0ULL; }

    for (int s = 0; s < NSTAGE; s++) {
        if (s == NSTAGE - 1) { CP_WAIT0(); } else { CP_WAIT1(); }
        __syncthreads();
        const float* wb = w_s + (s & 1) * KS * 640;
        int kbase = s * KS;
#pragma unroll
        for (int kk = 0; kk < KS; kk++) {
            ull ap[4];
#pragma unroll
            for (int m = 0; m < 4; m++) {
                float a = x_s[(rbase + m) * 129 + kbase + kk];
                ap[m] = pk2(a, a);
            }
#pragma unroll
            for (int g = 0; g < 5; g++) {
                float4 bv = *(const float4*)&wb[kk * 640 + g * 128 + cbase];
                ull blo = pk2(bv.x, bv.y), bhi = pk2(bv.z, bv.w);
#pragma unroll
                for (int m = 0; m < 4; m++) {
                    fma2(acc[m][g][0], ap[m], blo);
                    fma2(acc[m][g][1], ap[m], bhi);
                }
            }
        }
        __syncthreads();
        if (s + 2 < NSTAGE) {
            const float4* g4 = (const float4*)(Whh + (s + 2) * KS * 640);
            float* dst = w_s + (s & 1) * KS * 640;
#pragma unroll
            for (int j = 0; j < 5; j++) { int idx = t + j * 256; cp16(dst + idx * 4, g4 + idx); }
            CP_COMMIT();
        }
    }

    // Epilogue: all 5 gates already in registers.
    float bi[5][4];
#pragma unroll
    for (int g = 0; g < 5; g++) {
        float4 bv = *(const float4*)&bhh[g * 128 + cbase];
        bi[g][0] = 2.0f * bv.x; bi[g][1] = 2.0f * bv.y;
        bi[g][2] = 2.0f * bv.z; bi[g][3] = 2.0f * bv.w;
    }
#pragma unroll
    for (int m = 0; m < 4; m++) {
        int rr = rbase + m;
        float4 l4 = *(const float4*)&hl_s[rr * 132 + cbase];
        float4 r4 = *(const float4*)&hr_s[rr * 132 + cbase];
        float sv[5][4];
#pragma unroll
        for (int g = 0; g < 5; g++) {
            float2 lo = upk2(acc[m][g][0]), hi = upk2(acc[m][g][1]);
            sv[g][0] = lo.x + bi[g][0]; sv[g][1] = lo.y + bi[g][1];
            sv[g][2] = hi.x + bi[g][2]; sv[g][3] = hi.y + bi[g][3];
        }
        float hl4[4] = {l4.x, l4.y, l4.z, l4.w};
        float hr4[4] = {r4.x, r4.y, r4.z, r4.w};
        float ov[4];
#pragma unroll
        for (int j = 0; j < 4; j++) {
            float ig = sigf(sv[0][j]);
            float lf = sigf(sv[1][j]);
            float rf = sigf(sv[2][j]);
            float og = sigf(sv[3][j]);
            float gg = tanh_f(sv[4][j]);
            float cc = ig * gg + lf * hl4[j] + rf * hr4[j];
            ov[j] = og * tanh_f(cc);
        }
        *(float4*)&hout[(long long)(r0 + rr) * 128 + cbase] =
            make_float4(ov[0], ov[1], ov[2], ov[3]);
    }
}

// ---------------- launcher ----------------
extern "C" void kernel_launch(void* const* d_in, const int* in_sizes, int n_in,
                              void* d_out, int out_size) {
    const int* ids = (const int*)d_in[0];
    const float* emb = (const float*)d_in[1];
    const float* Wwh = (const float*)d_in[2];
    const float* Whh = (const float*)d_in[3];
    const float* bhh = (const float*)d_in[4];
    float* out = (float*)d_out;

    const int smem_embed = (64 * 129 + 128 * 128) * 4;                   // 98560
    const int smem_comb  = (32 * 129 + 2 * 32 * 132 + 2 * KS * 640) * 4; // 91264
    cudaFuncSetAttribute(embed_gemm, cudaFuncAttributeMaxDynamicSharedMemorySize, smem_embed);
    cudaFuncSetAttribute(combine2, cudaFuncAttributeMaxDynamicSharedMemorySize, smem_comb);

    // Stage 0: 131072 rows / 64 per block
    embed_gemm<<<(BB_ * LL_) / 64, 256, smem_embed>>>(ids, emb, Wwh);

    // Tree levels t = 1..11, n_half = 2048 >> t
    for (int tlev = 1; tlev <= 11; ++tlev) {
        int n_half = LL_ >> tlev;
        int rows = BB_ * n_half;
        int lg = 11 - tlev;  // log2(n_half)
        int src_sel = (tlev & 1) ? 0 : 1;
        int dst_sel = (tlev == 11) ? 2 : ((tlev & 1) ? 1 : 0);
        int blocks = rows / 32;
        combine2<<<blocks, 256, smem_comb>>>(src_sel, out, dst_sel, Whh, bhh, lg);
    }
}

// round 4
// speedup vs baseline: 1.9394x; 1.3961x over previous
#include <cuda_runtime.h>
#include <cuda_bf16.h>

#define BB_ 64
#define LL_ 2048

typedef unsigned long long ull;
typedef unsigned int u32;

// Ping-pong buffers for the tree levels.
__device__ float g_bufA[BB_ * LL_ * 128];        // 67 MB
__device__ float g_bufB[BB_ * (LL_ / 2) * 128];  // 33.5 MB
// Permuted split W_hh: [chunk(2)][n(320)][k(128)] bf16, n = gate*64 + within-chunk col
__device__ __align__(16) __nv_bfloat16 g_Whi[2 * 320 * 128];
__device__ __align__(16) __nv_bfloat16 g_Wlo[2 * 320 * 128];
// Split W_wh transposed: [n(128)][k(128)]
__device__ __align__(16) __nv_bfloat16 g_Ehi[128 * 128];
__device__ __align__(16) __nv_bfloat16 g_Elo[128 * 128];

extern __shared__ float smem[];

// ---------------- scalar helpers ----------------
__device__ __forceinline__ ull pk2(float lo, float hi) {
    ull r; asm("mov.b64 %0, {%1, %2};" : "=l"(r) : "f"(lo), "f"(hi)); return r;
}
__device__ __forceinline__ void fma2(ull& d, ull a, ull b) {
    asm("fma.rn.f32x2 %0, %1, %2, %0;" : "+l"(d) : "l"(a), "l"(b));
}
__device__ __forceinline__ float2 upk2(ull v) {
    float2 r; asm("mov.b64 {%0, %1}, %2;" : "=f"(r.x), "=f"(r.y) : "l"(v)); return r;
}
__device__ __forceinline__ float sigf(float x) { return 1.0f / (1.0f + __expf(-x)); }
__device__ __forceinline__ float tanh_f(float x) {
    return 1.0f - 2.0f / (__expf(2.0f * x) + 1.0f);
}

// ---------------- cp.async (FFMA fallback kernel) ----------------
__device__ __forceinline__ void cp16(float* s, const float4* g) {
    unsigned a = (unsigned)__cvta_generic_to_shared(s);
    asm volatile("cp.async.cg.shared.global [%0], [%1], 16;" :: "r"(a), "l"(g));
}
#define CP_COMMIT() asm volatile("cp.async.commit_group;")
#define CP_WAIT1()  asm volatile("cp.async.wait_group 1;")
#define CP_WAIT0()  asm volatile("cp.async.wait_group 0;")

// ---------------- mma.sync helpers ----------------
__device__ __forceinline__ u32 smem_u32(const void* p) {
    u32 a;
    asm("{ .reg .u64 t; cvta.to.shared.u64 t, %1; cvt.u32.u64 %0, t; }" : "=r"(a) : "l"(p));
    return a;
}
__device__ __forceinline__ void ldsm4(u32* r, u32 saddr) {
    asm volatile("ldmatrix.sync.aligned.m8n8.x4.shared.b16 {%0,%1,%2,%3}, [%4];"
                 : "=r"(r[0]), "=r"(r[1]), "=r"(r[2]), "=r"(r[3]) : "r"(saddr));
}
__device__ __forceinline__ void mma16816(float* d, const u32* a, u32 b0, u32 b1) {
    asm volatile(
        "mma.sync.aligned.m16n8k16.row.col.f32.bf16.bf16.f32 "
        "{%0,%1,%2,%3}, {%4,%5,%6,%7}, {%8,%9}, {%0,%1,%2,%3};"
        : "+f"(d[0]), "+f"(d[1]), "+f"(d[2]), "+f"(d[3])
        : "r"(a[0]), "r"(a[1]), "r"(a[2]), "r"(a[3]), "r"(b0), "r"(b1));
}

// =====================================================================
// Prep kernels: split weights to bf16 hi/lo.
// =====================================================================
__global__ void prep_w(const float* __restrict__ Whh) {
    int idx = blockIdx.x * 256 + threadIdx.x;  // over 128*640
    if (idx >= 128 * 640) return;
    int k = idx / 640, col = idx - k * 640;
    int g = col >> 7, c = col & 127;
    int chunk = c >> 6, cl = c & 63;
    int n = g * 64 + cl;
    float w = Whh[idx];
    __nv_bfloat16 hi = __float2bfloat16_rn(w);
    __nv_bfloat16 lo = __float2bfloat16_rn(w - __bfloat162float(hi));
    int dst = (chunk * 320 + n) * 128 + k;
    g_Whi[dst] = hi;
    g_Wlo[dst] = lo;
}
__global__ void prep_e(const float* __restrict__ Wwh) {
    int idx = blockIdx.x * 256 + threadIdx.x;  // over 128*128
    if (idx >= 128 * 128) return;
    int k = idx >> 7, n = idx & 127;
    float w = Wwh[idx];
    __nv_bfloat16 hi = __float2bfloat16_rn(w);
    __nv_bfloat16 lo = __float2bfloat16_rn(w - __bfloat162float(hi));
    g_Ehi[n * 128 + k] = hi;
    g_Elo[n * 128 + k] = lo;
}

// =====================================================================
// Embed via mma.sync: h0 = emb[ids] @ W_wh. CTA M=128, N=128, K=128.
// smem: Ahi(32KB) Alo(32KB) Bhi(32KB) Blo(32KB) = 128KB, XOR-swizzled.
// =====================================================================
__global__ __launch_bounds__(512, 1) void embed_mma(const int* __restrict__ ids,
                                                    const float* __restrict__ emb) {
    char* sm = (char*)smem;
    int t = threadIdx.x;
    int r0 = blockIdx.x * 128;

    // A: gather + split. Each i -> (row rr, 4 floats at k=c4*4).
    for (int i = t; i < 128 * 32; i += 512) {
        int rr = i >> 5, c4 = i & 31;
        int id = ids[r0 + rr];
        float4 v = ((const float4*)emb)[(long long)id * 32 + c4];
        float xv[4] = {v.x, v.y, v.z, v.w};
        __nv_bfloat16 hi[4], lo[4];
#pragma unroll
        for (int j = 0; j < 4; j++) {
            hi[j] = __float2bfloat16_rn(xv[j]);
            lo[j] = __float2bfloat16_rn(xv[j] - __bfloat162float(hi[j]));
        }
        u32 kp0 = (u32)(2 * c4);
        u32 sw = kp0 ^ ((rr & 7) << 2);
        *(uint2*)(sm + (rr * 64 + sw) * 4) = *(uint2*)hi;
        *(uint2*)(sm + 32768 + (rr * 64 + sw) * 4) = *(uint2*)lo;
    }
    // B: copy split W (uint4 = 4 kpairs).
    for (int j = t; j < 2 * 128 * 16; j += 512) {
        int split = j >> 11, rem = j & 2047;
        int row = rem >> 4, q = rem & 15;
        const __nv_bfloat16* src = split ? g_Elo : g_Ehi;
        uint4 v = *(const uint4*)&src[row * 128 + q * 8];
        u32 kpb = (u32)(4 * q) ^ ((row & 7) << 2);
        *(uint4*)(sm + 65536 + split * 32768 + (row * 64 + kpb) * 4) = v;
    }
    __syncthreads();

    u32 smb = smem_u32(sm);
    int lane = t & 31, warp = t >> 5;
    int wm = warp >> 2, wn = warp & 3;
    int tile = lane >> 3, l7 = lane & 7;
    u32 xsw = (u32)(l7 << 2);
    int arow = wm * 32 + (tile & 1) * 8 + l7;   // + mf*16
    u32 tka = (u32)((tile >> 1) * 4);
    int brow = wn * 32 + (tile >> 1) * 8 + l7;  // + np*16
    u32 tkb = (u32)((tile & 1) * 4);

    float acc[2][4][4];
#pragma unroll
    for (int a = 0; a < 2; a++)
#pragma unroll
        for (int b = 0; b < 4; b++)
#pragma unroll
            for (int c = 0; c < 4; c++) acc[a][b][c] = 0.0f;

#pragma unroll 1
    for (int ks = 0; ks < 8; ks++) {
#pragma unroll
        for (int split = 0; split < 3; split++) {
            u32 abase = smb + ((split == 2) ? 32768u : 0u);
            u32 bbase = smb + 65536u + ((split == 1) ? 32768u : 0u);
            u32 ka = (((u32)(ks * 8) + tka) ^ xsw) * 4;
            u32 kb = (((u32)(ks * 8) + tkb) ^ xsw) * 4;
            u32 af[2][4];
            ldsm4(af[0], abase + (u32)arow * 256 + ka);
            ldsm4(af[1], abase + (u32)(arow + 16) * 256 + ka);
#pragma unroll
            for (int np = 0; np < 2; np++) {
                u32 bf[4];
                ldsm4(bf, bbase + (u32)(brow + np * 16) * 256 + kb);
                mma16816(acc[0][2 * np], af[0], bf[0], bf[1]);
                mma16816(acc[0][2 * np + 1], af[0], bf[2], bf[3]);
                mma16816(acc[1][2 * np], af[1], bf[0], bf[1]);
                mma16816(acc[1][2 * np + 1], af[1], bf[2], bf[3]);
            }
        }
    }

    int grp = lane >> 2, tid = lane & 3;
#pragma unroll
    for (int mf = 0; mf < 2; mf++)
#pragma unroll
        for (int nf = 0; nf < 4; nf++) {
            int row = r0 + wm * 32 + mf * 16 + grp;
            int col = wn * 32 + nf * 8 + tid * 2;
            *(float2*)&g_bufA[(long long)row * 128 + col] =
                make_float2(acc[mf][nf][0], acc[mf][nf][1]);
            *(float2*)&g_bufA[(long long)(row + 8) * 128 + col] =
                make_float2(acc[mf][nf][2], acc[mf][nf][3]);
        }
}

// =====================================================================
// Tree level via mma.sync: CTA = 128 rows x 320 permuted cols (chunk), K=128.
// Split bf16: hi*hi + hi*lo + lo*hi, fp32 accum. Fused LSTM epilogue via
// smem s-buffer (reuses B region). smem = 231424 B.
// =====================================================================
#define CB_B 65536
#define CB_SM (65536 + 165888)

__global__ __launch_bounds__(512, 1) void combine_mma(int src_sel,
                                                      float* __restrict__ out_param,
                                                      int dst_sel,
                                                      const float* __restrict__ bhh,
                                                      int lg_nhalf) {
    char* sm = (char*)smem;
    int t = threadIdx.x;
    int chunk = blockIdx.y;
    int r0 = blockIdx.x * 128;
    int n_half = 1 << lg_nhalf;

    const float* hin = (src_sel == 0) ? g_bufA : g_bufB;
    float* hout = (dst_sel == 0) ? g_bufA : (dst_sel == 1) ? g_bufB : out_param;

    // A: x = hl + hr, split, swizzled.
    const float4* hin4 = (const float4*)hin;
    for (int i = t; i < 128 * 32; i += 512) {
        int rr = i >> 5, c4 = i & 31;
        int r = r0 + rr;
        int b = r >> lg_nhalf;
        int ii = r - (b << lg_nhalf);
        long long base = (long long)b * (2 * n_half);
        float4 l4 = hin4[(base + 2 * ii) * 32 + c4];
        float4 r4 = hin4[(base + 2 * ii + 1) * 32 + c4];
        float xv[4] = {l4.x + r4.x, l4.y + r4.y, l4.z + r4.z, l4.w + r4.w};
        __nv_bfloat16 hi[4], lo[4];
#pragma unroll
        for (int j = 0; j < 4; j++) {
            hi[j] = __float2bfloat16_rn(xv[j]);
            lo[j] = __float2bfloat16_rn(xv[j] - __bfloat162float(hi[j]));
        }
        u32 kp0 = (u32)(2 * c4);
        u32 sw = kp0 ^ ((rr & 7) << 2);
        *(uint2*)(sm + (rr * 64 + sw) * 4) = *(uint2*)hi;
        *(uint2*)(sm + 32768 + (rr * 64 + sw) * 4) = *(uint2*)lo;
    }
    // B: split W tiles [320][64 u32] x 2, swizzled.
    for (int j = t; j < 2 * 320 * 16; j += 512) {
        int split = j / 5120, rem = j - split * 5120;
        int row = rem >> 4, q = rem & 15;
        const __nv_bfloat16* src = split ? g_Wlo : g_Whi;
        uint4 v = *(const uint4*)&src[(chunk * 320 + row) * 128 + q * 8];
        u32 kpb = (u32)(4 * q) ^ ((row & 7) << 2);
        *(uint4*)(sm + CB_B + split * 81920 + (row * 64 + kpb) * 4) = v;
    }
    __syncthreads();

    u32 smb = smem_u32(sm);
    int lane = t & 31, warp = t >> 5;
    int wm = warp >> 2, wn = warp & 3;
    int tile = lane >> 3, l7 = lane & 7;
    u32 xsw = (u32)(l7 << 2);
    int arow = wm * 32 + (tile & 1) * 8 + l7;
    u32 tka = (u32)((tile >> 1) * 4);
    int brow = wn * 80 + (tile >> 1) * 8 + l7;
    u32 tkb = (u32)((tile & 1) * 4);

    float acc[2][10][4];
#pragma unroll
    for (int a = 0; a < 2; a++)
#pragma unroll
        for (int b = 0; b < 10; b++)
#pragma unroll
            for (int c = 0; c < 4; c++) acc[a][b][c] = 0.0f;

#pragma unroll 1
    for (int ks = 0; ks < 8; ks++) {
#pragma unroll
        for (int split = 0; split < 3; split++) {
            u32 abase = smb + ((split == 2) ? 32768u : 0u);
            u32 bbase = smb + CB_B + ((split == 1) ? 81920u : 0u);
            u32 ka = (((u32)(ks * 8) + tka) ^ xsw) * 4;
            u32 kb = (((u32)(ks * 8) + tkb) ^ xsw) * 4;
            u32 af[2][4];
            ldsm4(af[0], abase + (u32)arow * 256 + ka);
            ldsm4(af[1], abase + (u32)(arow + 16) * 256 + ka);
#pragma unroll
            for (int np = 0; np < 5; np++) {
                u32 bf[4];
                ldsm4(bf, bbase + (u32)(brow + np * 16) * 256 + kb);
                mma16816(acc[0][2 * np], af[0], bf[0], bf[1]);
                mma16816(acc[0][2 * np + 1], af[0], bf[2], bf[3]);
                mma16816(acc[1][2 * np], af[1], bf[0], bf[1]);
                mma16816(acc[1][2 * np + 1], af[1], bf[2], bf[3]);
            }
        }
    }

    // Stage s into smem (reuse B region), pitch 324 floats.
    __syncthreads();
    float* sS = (float*)(sm + CB_B);
    int grp = lane >> 2, tid = lane & 3;
#pragma unroll
    for (int mf = 0; mf < 2; mf++)
#pragma unroll
        for (int nf = 0; nf < 10; nf++) {
            int row = wm * 32 + mf * 16 + grp;
            int col = wn * 80 + nf * 8 + tid * 2;
            *(float2*)&sS[row * 324 + col] = make_float2(acc[mf][nf][0], acc[mf][nf][1]);
            *(float2*)&sS[(row + 8) * 324 + col] = make_float2(acc[mf][nf][2], acc[mf][nf][3]);
        }
    __syncthreads();

    // Epilogue: thread -> (row = t>>2, 16 cols).
    {
        int row = t >> 2;
        int cb = (t & 3) * 16;
        int r = r0 + row;
        int b = r >> lg_nhalf;
        int ii = r - (b << lg_nhalf);
        long long rowL = (long long)b * (2 * n_half) + 2 * ii;
        const float* hlp = &hin[rowL * 128 + chunk * 64];
        const float* hrp = &hin[(rowL + 1) * 128 + chunk * 64];
        float* hop = &hout[(long long)r * 128 + chunk * 64];
        const float* srow = &sS[row * 324];
#pragma unroll
        for (int i = 0; i < 16; i += 4) {
            int cl = cb + i;
            float4 s0 = *(const float4*)&srow[0 * 64 + cl];
            float4 s1 = *(const float4*)&srow[1 * 64 + cl];
            float4 s2 = *(const float4*)&srow[2 * 64 + cl];
            float4 s3 = *(const float4*)&srow[3 * 64 + cl];
            float4 s4 = *(const float4*)&srow[4 * 64 + cl];
            float4 b0 = *(const float4*)&bhh[0 * 128 + chunk * 64 + cl];
            float4 b1 = *(const float4*)&bhh[1 * 128 + chunk * 64 + cl];
            float4 b2 = *(const float4*)&bhh[2 * 128 + chunk * 64 + cl];
            float4 b3 = *(const float4*)&bhh[3 * 128 + chunk * 64 + cl];
            float4 b4 = *(const float4*)&bhh[4 * 128 + chunk * 64 + cl];
            float4 l4 = *(const float4*)&hlp[cl];
            float4 r4 = *(const float4*)&hrp[cl];
            float si[4] = {s0.x + 2.f * b0.x, s0.y + 2.f * b0.y, s0.z + 2.f * b0.z, s0.w + 2.f * b0.w};
            float slf[4] = {s1.x + 2.f * b1.x, s1.y + 2.f * b1.y, s1.z + 2.f * b1.z, s1.w + 2.f * b1.w};
            float srf[4] = {s2.x + 2.f * b2.x, s2.y + 2.f * b2.y, s2.z + 2.f * b2.z, s2.w + 2.f * b2.w};
            float so[4] = {s3.x + 2.f * b3.x, s3.y + 2.f * b3.y, s3.z + 2.f * b3.z, s3.w + 2.f * b3.w};
            float sg[4] = {s4.x + 2.f * b4.x, s4.y + 2.f * b4.y, s4.z + 2.f * b4.z, s4.w + 2.f * b4.w};
            float hl4[4] = {l4.x, l4.y, l4.z, l4.w};
            float hr4[4] = {r4.x, r4.y, r4.z, r4.w};
            float ov[4];
#pragma unroll
            for (int j = 0; j < 4; j++) {
                float cc = sigf(si[j]) * tanh_f(sg[j]) + sigf(slf[j]) * hl4[j] + sigf(srf[j]) * hr4[j];
                ov[j] = sigf(so[j]) * tanh_f(cc);
            }
            *(float4*)&hop[cl] = make_float4(ov[0], ov[1], ov[2], ov[3]);
        }
    }
}

// =====================================================================
// FFMA fallback combine (round 2) — final 64-row level.
// =====================================================================
#define KS 8
#define NSTAGE 16

__global__ __launch_bounds__(256, 2) void combine2(int src_sel, float* __restrict__ out_param,
                                                   int dst_sel,
                                                   const float* __restrict__ Whh,
                                                   const float* __restrict__ bhh,
                                                   int lg_nhalf) {
    float* x_s  = smem;
    float* hl_s = x_s + 32 * 129;
    float* hr_s = hl_s + 32 * 132;
    float* w_s  = hr_s + 32 * 132;

    const float* hin = (src_sel == 0) ? g_bufA : g_bufB;
    float* hout = (dst_sel == 0) ? g_bufA : (dst_sel == 1) ? g_bufB : out_param;

    int t = threadIdx.x;
    int r0 = blockIdx.x * 32;
    int n_half = 1 << lg_nhalf;

    {
        const float4* g0 = (const float4*)(Whh);
        float* d0 = w_s;
#pragma unroll
        for (int j = 0; j < 5; j++) { int idx = t + j * 256; cp16(d0 + idx * 4, g0 + idx); }
        CP_COMMIT();
        const float4* g1 = (const float4*)(Whh + KS * 640);
        float* d1 = w_s + KS * 640;
#pragma unroll
        for (int j = 0; j < 5; j++) { int idx = t + j * 256; cp16(d1 + idx * 4, g1 + idx); }
        CP_COMMIT();
    }

    const float4* hin4 = (const float4*)hin;
    for (int i = t; i < 32 * 32; i += 256) {
        int rr = i >> 5, c4 = i & 31;
        int r = r0 + rr;
        int b = r >> lg_nhalf;
        int ii = r - (b << lg_nhalf);
        long long base = (long long)b * (2 * n_half);
        float4 l4 = hin4[(base + 2 * ii) * 32 + c4];
        float4 r4 = hin4[(base + 2 * ii + 1) * 32 + c4];
        *(float4*)&hl_s[rr * 132 + c4 * 4] = l4;
        *(float4*)&hr_s[rr * 132 + c4 * 4] = r4;
        float* xp = &x_s[rr * 129 + c4 * 4];
        xp[0] = l4.x + r4.x; xp[1] = l4.y + r4.y; xp[2] = l4.z + r4.z; xp[3] = l4.w + r4.w;
    }

    int lane = t & 31, warp = t >> 5;
    int wy = warp >> 2, wx = warp & 3;
    int rowg = lane >> 3, colg = lane & 7;
    int rbase = wy * 16 + rowg * 4;
    int cbase = wx * 32 + colg * 4;

    ull acc[4][5][2];
#pragma unroll
    for (int m = 0; m < 4; m++)
#pragma unroll
        for (int g = 0; g < 5; g++) { acc[m][g][0] = 0ULL; acc[m][g][1] = 0ULL; }

    for (int s = 0; s < NSTAGE; s++) {
        if (s == NSTAGE - 1) { CP_WAIT0(); } else { CP_WAIT1(); }
        __syncthreads();
        const float* wb = w_s + (s & 1) * KS * 640;
        int kbase = s * KS;
#pragma unroll
        for (int kk = 0; kk < KS; kk++) {
            ull ap[4];
#pragma unroll
            for (int m = 0; m < 4; m++) {
                float a = x_s[(rbase + m) * 129 + kbase + kk];
                ap[m] = pk2(a, a);
            }
#pragma unroll
            for (int g = 0; g < 5; g++) {
                float4 bv = *(const float4*)&wb[kk * 640 + g * 128 + cbase];
                ull blo = pk2(bv.x, bv.y), bhi = pk2(bv.z, bv.w);
#pragma unroll
                for (int m = 0; m < 4; m++) {
                    fma2(acc[m][g][0], ap[m], blo);
                    fma2(acc[m][g][1], ap[m], bhi);
                }
            }
        }
        __syncthreads();
        if (s + 2 < NSTAGE) {
            const float4* g4 = (const float4*)(Whh + (s + 2) * KS * 640);
            float* dst = w_s + (s & 1) * KS * 640;
#pragma unroll
            for (int j = 0; j < 5; j++) { int idx = t + j * 256; cp16(dst + idx * 4, g4 + idx); }
            CP_COMMIT();
        }
    }

    float bi[5][4];
#pragma unroll
    for (int g = 0; g < 5; g++) {
        float4 bv = *(const float4*)&bhh[g * 128 + cbase];
        bi[g][0] = 2.0f * bv.x; bi[g][1] = 2.0f * bv.y;
        bi[g][2] = 2.0f * bv.z; bi[g][3] = 2.0f * bv.w;
    }
#pragma unroll
    for (int m = 0; m < 4; m++) {
        int rr = rbase + m;
        float4 l4 = *(const float4*)&hl_s[rr * 132 + cbase];
        float4 r4 = *(const float4*)&hr_s[rr * 132 + cbase];
        float sv[5][4];
#pragma unroll
        for (int g = 0; g < 5; g++) {
            float2 lo = upk2(acc[m][g][0]), hi = upk2(acc[m][g][1]);
            sv[g][0] = lo.x + bi[g][0]; sv[g][1] = lo.y + bi[g][1];
            sv[g][2] = hi.x + bi[g][2]; sv[g][3] = hi.y + bi[g][3];
        }
        float hl4[4] = {l4.x, l4.y, l4.z, l4.w};
        float hr4[4] = {r4.x, r4.y, r4.z, r4.w};
        float ov[4];
#pragma unroll
        for (int j = 0; j < 4; j++) {
            float ig = sigf(sv[0][j]);
            float lf = sigf(sv[1][j]);
            float rf = sigf(sv[2][j]);
            float og = sigf(sv[3][j]);
            float gg = tanh_f(sv[4][j]);
            float cc = ig * gg + lf * hl4[j] + rf * hr4[j];
            ov[j] = og * tanh_f(cc);
        }
        *(float4*)&hout[(long long)(r0 + rr) * 128 + cbase] =
            make_float4(ov[0], ov[1], ov[2], ov[3]);
    }
}

// ---------------- launcher ----------------
extern "C" void kernel_launch(void* const* d_in, const int* in_sizes, int n_in,
                              void* d_out, int out_size) {
    const int* ids = (const int*)d_in[0];
    const float* emb = (const float*)d_in[1];
    const float* Wwh = (const float*)d_in[2];
    const float* Whh = (const float*)d_in[3];
    const float* bhh = (const float*)d_in[4];
    float* out = (float*)d_out;

    const int smem_embed = 131072;
    const int smem_comb_mma = CB_SM;  // 231424
    const int smem_comb2 = (32 * 129 + 2 * 32 * 132 + 2 * KS * 640) * 4;
    cudaFuncSetAttribute(embed_mma, cudaFuncAttributeMaxDynamicSharedMemorySize, smem_embed);
    cudaFuncSetAttribute(combine_mma, cudaFuncAttributeMaxDynamicSharedMemorySize, smem_comb_mma);
    cudaFuncSetAttribute(combine2, cudaFuncAttributeMaxDynamicSharedMemorySize, smem_comb2);

    prep_w<<<(128 * 640 + 255) / 256, 256>>>(Whh);
    prep_e<<<(128 * 128 + 255) / 256, 256>>>(Wwh);
    embed_mma<<<(BB_ * LL_) / 128, 512, smem_embed>>>(ids, emb);

    for (int tlev = 1; tlev <= 11; ++tlev) {
        int n_half = LL_ >> tlev;
        int rows = BB_ * n_half;
        int lg = 11 - tlev;
        int src_sel = (tlev & 1) ? 0 : 1;
        int dst_sel = (tlev == 11) ? 2 : ((tlev & 1) ? 1 : 0);
        if (tlev <= 10) {
            dim3 grid(rows / 128, 2);
            combine_mma<<<grid, 512, smem_comb_mma>>>(src_sel, out, dst_sel, bhh, lg);
        } else {
            combine2<<<rows / 32, 256, smem_comb2>>>(src_sel, out, dst_sel, Whh, bhh, lg);
        }
    }
}

// round 5
// speedup vs baseline: 2.4521x; 1.2643x over previous
#include <cuda_runtime.h>
#include <cuda_bf16.h>

#define BB_ 64
#define LL_ 2048

typedef unsigned long long ull;
typedef unsigned int u32;

// Ping-pong buffers for the tree levels.
__device__ float g_bufA[BB_ * LL_ * 128];        // 67 MB
__device__ float g_bufB[BB_ * (LL_ / 2) * 128];  // 33.5 MB
// Permuted split W_hh: [chunk(2)][n(320)][k(128)] bf16, n = gate*64 + within-chunk col
__device__ __align__(16) __nv_bfloat16 g_Whi[2 * 320 * 128];
__device__ __align__(16) __nv_bfloat16 g_Wlo[2 * 320 * 128];
// Split W_wh transposed: [n(128)][k(128)]
__device__ __align__(16) __nv_bfloat16 g_Ehi[128 * 128];
__device__ __align__(16) __nv_bfloat16 g_Elo[128 * 128];

extern __shared__ float smem[];

// ---------------- scalar helpers ----------------
__device__ __forceinline__ ull pk2(float lo, float hi) {
    ull r; asm("mov.b64 %0, {%1, %2};" : "=l"(r) : "f"(lo), "f"(hi)); return r;
}
__device__ __forceinline__ void fma2(ull& d, ull a, ull b) {
    asm("fma.rn.f32x2 %0, %1, %2, %0;" : "+l"(d) : "l"(a), "l"(b));
}
__device__ __forceinline__ float2 upk2(ull v) {
    float2 r; asm("mov.b64 {%0, %1}, %2;" : "=f"(r.x), "=f"(r.y) : "l"(v)); return r;
}
__device__ __forceinline__ float sigf(float x) { return 1.0f / (1.0f + __expf(-x)); }
__device__ __forceinline__ float tanh_f(float x) {
    return 1.0f - 2.0f / (__expf(2.0f * x) + 1.0f);
}

// ---------------- cp.async ----------------
__device__ __forceinline__ void cp16(void* s, const void* g) {
    unsigned a = (unsigned)__cvta_generic_to_shared(s);
    asm volatile("cp.async.cg.shared.global [%0], [%1], 16;" :: "r"(a), "l"(g));
}
#define CP_COMMIT() asm volatile("cp.async.commit_group;")
#define CP_WAIT1()  asm volatile("cp.async.wait_group 1;")
#define CP_WAIT0()  asm volatile("cp.async.wait_group 0;")

// ---------------- mma.sync helpers ----------------
__device__ __forceinline__ u32 smem_u32(const void* p) {
    u32 a;
    asm("{ .reg .u64 t; cvta.to.shared.u64 t, %1; cvt.u32.u64 %0, t; }" : "=r"(a) : "l"(p));
    return a;
}
__device__ __forceinline__ void ldsm4(u32* r, u32 saddr) {
    asm volatile("ldmatrix.sync.aligned.m8n8.x4.shared.b16 {%0,%1,%2,%3}, [%4];"
                 : "=r"(r[0]), "=r"(r[1]), "=r"(r[2]), "=r"(r[3]) : "r"(saddr));
}
__device__ __forceinline__ void mma16816(float* d, const u32* a, u32 b0, u32 b1) {
    asm volatile(
        "mma.sync.aligned.m16n8k16.row.col.f32.bf16.bf16.f32 "
        "{%0,%1,%2,%3}, {%4,%5,%6,%7}, {%8,%9}, {%0,%1,%2,%3};"
        : "+f"(d[0]), "+f"(d[1]), "+f"(d[2]), "+f"(d[3])
        : "r"(a[0]), "r"(a[1]), "r"(a[2]), "r"(a[3]), "r"(b0), "r"(b1));
}

// =====================================================================
// Prep kernels: split weights to bf16 hi/lo.
// =====================================================================
__global__ void prep_w(const float* __restrict__ Whh) {
    int idx = blockIdx.x * 256 + threadIdx.x;  // over 128*640
    if (idx >= 128 * 640) return;
    int k = idx / 640, col = idx - k * 640;
    int g = col >> 7, c = col & 127;
    int chunk = c >> 6, cl = c & 63;
    int n = g * 64 + cl;
    float w = Whh[idx];
    __nv_bfloat16 hi = __float2bfloat16_rn(w);
    __nv_bfloat16 lo = __float2bfloat16_rn(w - __bfloat162float(hi));
    int dst = (chunk * 320 + n) * 128 + k;
    g_Whi[dst] = hi;
    g_Wlo[dst] = lo;
}
__global__ void prep_e(const float* __restrict__ Wwh) {
    int idx = blockIdx.x * 256 + threadIdx.x;  // over 128*128
    if (idx >= 128 * 128) return;
    int k = idx >> 7, n = idx & 127;
    float w = Wwh[idx];
    __nv_bfloat16 hi = __float2bfloat16_rn(w);
    __nv_bfloat16 lo = __float2bfloat16_rn(w - __bfloat162float(hi));
    g_Ehi[n * 128 + k] = hi;
    g_Elo[n * 128 + k] = lo;
}

// =====================================================================
// Embed via mma.sync: h0 = emb[ids] @ W_wh. CTA M=64, N=128, K=128.
// 256 thr, 8 warps (2x4), warp tile 32x32. smem 96KB -> 2 CTAs/SM.
// =====================================================================
__global__ __launch_bounds__(256, 2) void embed_mma(const int* __restrict__ ids,
                                                    const float* __restrict__ emb) {
    char* sm = (char*)smem;
    int t = threadIdx.x;
    int r0 = blockIdx.x * 64;

    // A: gather + split. smem: Ahi[0,16384), Alo[16384,32768)
    for (int i = t; i < 64 * 32; i += 256) {
        int rr = i >> 5, c4 = i & 31;
        int id = ids[r0 + rr];
        float4 v = ((const float4*)emb)[(long long)id * 32 + c4];
        float xv[4] = {v.x, v.y, v.z, v.w};
        __nv_bfloat16 hi[4], lo[4];
#pragma unroll
        for (int j = 0; j < 4; j++) {
            hi[j] = __float2bfloat16_rn(xv[j]);
            lo[j] = __float2bfloat16_rn(xv[j] - __bfloat162float(hi[j]));
        }
        u32 sw = (u32)(2 * c4) ^ ((rr & 7) << 2);
        *(uint2*)(sm + (rr * 64 + sw) * 4) = *(uint2*)hi;
        *(uint2*)(sm + 16384 + (rr * 64 + sw) * 4) = *(uint2*)lo;
    }
    // B: split W. smem: Bhi[32768,65536), Blo[65536,98304)
    for (int j = t; j < 2 * 128 * 16; j += 256) {
        int split = j >> 11, rem = j & 2047;
        int row = rem >> 4, q = rem & 15;
        const __nv_bfloat16* src = split ? g_Elo : g_Ehi;
        uint4 v = *(const uint4*)&src[row * 128 + q * 8];
        u32 kpb = (u32)(4 * q) ^ ((row & 7) << 2);
        *(uint4*)(sm + 32768 + split * 32768 + (row * 64 + kpb) * 4) = v;
    }
    __syncthreads();

    u32 smb = smem_u32(sm);
    int lane = t & 31, warp = t >> 5;
    int wm = warp >> 2, wn = warp & 3;  // 2 x 4
    int t8 = lane >> 3, l7 = lane & 7;
    u32 xsw = (u32)(l7 << 2);
    int arow = wm * 32 + (t8 & 1) * 8 + l7;
    u32 tka = (u32)((t8 >> 1) * 4);
    int brow = wn * 32 + (t8 >> 1) * 8 + l7;
    u32 tkb = (u32)((t8 & 1) * 4);

    float acc[2][4][4];
#pragma unroll
    for (int a = 0; a < 2; a++)
#pragma unroll
        for (int b = 0; b < 4; b++)
#pragma unroll
            for (int c = 0; c < 4; c++) acc[a][b][c] = 0.0f;

#pragma unroll 1
    for (int ks = 0; ks < 8; ks++) {
#pragma unroll
        for (int split = 0; split < 3; split++) {
            u32 abase = smb + ((split == 2) ? 16384u : 0u);
            u32 bbase = smb + 32768u + ((split == 1) ? 32768u : 0u);
            u32 ka = (((u32)(ks * 8) + tka) ^ xsw) * 4;
            u32 kb = (((u32)(ks * 8) + tkb) ^ xsw) * 4;
            u32 af[2][4];
            ldsm4(af[0], abase + (u32)arow * 256 + ka);
            ldsm4(af[1], abase + (u32)(arow + 16) * 256 + ka);
#pragma unroll
            for (int np = 0; np < 2; np++) {
                u32 bf[4];
                ldsm4(bf, bbase + (u32)(brow + np * 16) * 256 + kb);
                mma16816(acc[0][2 * np], af[0], bf[0], bf[1]);
                mma16816(acc[0][2 * np + 1], af[0], bf[2], bf[3]);
                mma16816(acc[1][2 * np], af[1], bf[0], bf[1]);
                mma16816(acc[1][2 * np + 1], af[1], bf[2], bf[3]);
            }
        }
    }

    int grp = lane >> 2, tid4 = lane & 3;
#pragma unroll
    for (int mf = 0; mf < 2; mf++)
#pragma unroll
        for (int nf = 0; nf < 4; nf++) {
            int row = r0 + wm * 32 + mf * 16 + grp;
            int col = wn * 32 + nf * 8 + tid4 * 2;
            *(float2*)&g_bufA[(long long)row * 128 + col] =
                make_float2(acc[mf][nf][0], acc[mf][nf][1]);
            *(float2*)&g_bufA[(long long)(row + 8) * 128 + col] =
                make_float2(acc[mf][nf][2], acc[mf][nf][3]);
        }
}

// =====================================================================
// Persistent tree-level kernel. Grid (<=74, 2 chunks). B resident in smem,
// each CTA loops over row-tiles. Gate-aligned warp mapping: warp wn owns
// cols [wn*16, wn*16+16) of ALL 5 gates -> epilogue fully in registers.
// smem: A 2x32KB | B 2x80KB | bias 1.25KB = 230656 B.
// =====================================================================
#define PB_B 65536
#define PB_BIAS 229376
#define PB_SM 230656

__global__ __launch_bounds__(512, 1) void combine_pers(int src_sel,
                                                       float* __restrict__ out_param,
                                                       int dst_sel,
                                                       const float* __restrict__ bhh,
                                                       int lg_nhalf, int ntiles) {
    char* sm = (char*)smem;
    int t = threadIdx.x;
    int chunk = blockIdx.y;
    int n_half = 1 << lg_nhalf;

    const float* hin = (src_sel == 0) ? g_bufA : g_bufB;
    float* hout = (dst_sel == 0) ? g_bufA : (dst_sel == 1) ? g_bufB : out_param;

    // B fill once via cp.async: [split(2)][row 320][16 uint4], swizzled.
    for (int j = t; j < 2 * 320 * 16; j += 512) {
        int split = j / 5120, rem = j - split * 5120;
        int row = rem >> 4, q = rem & 15;
        const __nv_bfloat16* src = split ? g_Wlo : g_Whi;
        u32 kpb = (u32)(4 * q) ^ ((row & 7) << 2);
        cp16(sm + PB_B + split * 81920 + (row * 64 + kpb) * 4,
             &src[(chunk * 320 + row) * 128 + q * 8]);
    }
    CP_COMMIT();
    // Chunk-local bias (pre-doubled): [g*64 + cl]
    float* bias_s = (float*)(sm + PB_BIAS);
    for (int j = t; j < 320; j += 512)
        bias_s[j] = 2.0f * bhh[(j >> 6) * 128 + chunk * 64 + (j & 63)];

    u32 smb = smem_u32(sm);
    int lane = t & 31, warp = t >> 5;
    int wm = warp >> 2, wn = warp & 3;  // 4 x 4
    int t8 = lane >> 3, l7 = lane & 7;
    u32 xsw = (u32)(l7 << 2);
    int arow = wm * 32 + (t8 & 1) * 8 + l7;
    u32 tka = (u32)((t8 >> 1) * 4);
    int brow0 = wn * 16 + (t8 >> 1) * 8 + l7;  // + g*64
    u32 tkb = (u32)((t8 & 1) * 4);
    int grp = lane >> 2, tid4 = lane & 3;

    const float4* hin4 = (const float4*)hin;

    for (int tile = blockIdx.x; tile < ntiles; tile += gridDim.x) {
        int r0 = tile * 128;
        __syncthreads();  // previous tile fully done before A overwrite

        // A fill: x = hl + hr, split bf16 hi/lo, swizzled.
        for (int i = t; i < 128 * 32; i += 512) {
            int rr = i >> 5, c4 = i & 31;
            int r = r0 + rr;
            int b = r >> lg_nhalf;
            int ii = r - (b << lg_nhalf);
            long long base = (long long)b * (2 * n_half);
            float4 l4 = hin4[(base + 2 * ii) * 32 + c4];
            float4 r4 = hin4[(base + 2 * ii + 1) * 32 + c4];
            float xv[4] = {l4.x + r4.x, l4.y + r4.y, l4.z + r4.z, l4.w + r4.w};
            __nv_bfloat16 hi[4], lo[4];
#pragma unroll
            for (int j = 0; j < 4; j++) {
                hi[j] = __float2bfloat16_rn(xv[j]);
                lo[j] = __float2bfloat16_rn(xv[j] - __bfloat162float(hi[j]));
            }
            u32 sw = (u32)(2 * c4) ^ ((rr & 7) << 2);
            *(uint2*)(sm + (rr * 64 + sw) * 4) = *(uint2*)hi;
            *(uint2*)(sm + 32768 + (rr * 64 + sw) * 4) = *(uint2*)lo;
        }
        CP_WAIT0();  // B ready (no-op after first tile)
        __syncthreads();

        // MMA: acc[mf(2)][gate(5)][nf2(2)][4]
        float acc[2][5][2][4];
#pragma unroll
        for (int a = 0; a < 2; a++)
#pragma unroll
            for (int g = 0; g < 5; g++)
#pragma unroll
                for (int n2 = 0; n2 < 2; n2++)
#pragma unroll
                    for (int c = 0; c < 4; c++) acc[a][g][n2][c] = 0.0f;

#pragma unroll 1
        for (int ks = 0; ks < 8; ks++) {
#pragma unroll
            for (int split = 0; split < 3; split++) {
                u32 abase = smb + ((split == 2) ? 32768u : 0u);
                u32 bbase = smb + PB_B + ((split == 1) ? 81920u : 0u);
                u32 ka = (((u32)(ks * 8) + tka) ^ xsw) * 4;
                u32 kb = (((u32)(ks * 8) + tkb) ^ xsw) * 4;
                u32 af[2][4];
                ldsm4(af[0], abase + (u32)arow * 256 + ka);
                ldsm4(af[1], abase + (u32)(arow + 16) * 256 + ka);
#pragma unroll
                for (int g = 0; g < 5; g++) {
                    u32 bf[4];
                    ldsm4(bf, bbase + (u32)(g * 64 + brow0) * 256 + kb);
                    mma16816(acc[0][g][0], af[0], bf[0], bf[1]);
                    mma16816(acc[0][g][1], af[0], bf[2], bf[3]);
                    mma16816(acc[1][g][0], af[1], bf[0], bf[1]);
                    mma16816(acc[1][g][1], af[1], bf[2], bf[3]);
                }
            }
        }

        // Epilogue: all gates in registers. 4 rows x 4 cols per thread.
#pragma unroll
        for (int mf = 0; mf < 2; mf++) {
#pragma unroll
            for (int half = 0; half < 2; half++) {
                int rr = wm * 32 + mf * 16 + grp + half * 8;
                int r = r0 + rr;
                int b = r >> lg_nhalf;
                int ii = r - (b << lg_nhalf);
                long long rowL = (long long)b * (2 * n_half) + 2 * ii;
                const float* hlp = &hin[rowL * 128 + chunk * 64];
                const float* hrp = &hin[(rowL + 1) * 128 + chunk * 64];
                float* hop = &hout[(long long)r * 128 + chunk * 64];
#pragma unroll
                for (int n2 = 0; n2 < 2; n2++) {
                    int cl = wn * 16 + n2 * 8 + tid4 * 2;
                    float2 hlv = *(const float2*)&hlp[cl];
                    float2 hrv = *(const float2*)&hrp[cl];
                    float hl2[2] = {hlv.x, hlv.y};
                    float hr2[2] = {hrv.x, hrv.y};
                    float ov[2];
#pragma unroll
                    for (int j = 0; j < 2; j++) {
                        int e = half * 2 + j;
                        float si = acc[mf][0][n2][e] + bias_s[0 * 64 + cl + j];
                        float sl = acc[mf][1][n2][e] + bias_s[1 * 64 + cl + j];
                        float sr = acc[mf][2][n2][e] + bias_s[2 * 64 + cl + j];
                        float so = acc[mf][3][n2][e] + bias_s[3 * 64 + cl + j];
                        float sg = acc[mf][4][n2][e] + bias_s[4 * 64 + cl + j];
                        float cc = sigf(si) * tanh_f(sg) + sigf(sl) * hl2[j] + sigf(sr) * hr2[j];
                        ov[j] = sigf(so) * tanh_f(cc);
                    }
                    *(float2*)&hop[cl] = make_float2(ov[0], ov[1]);
                }
            }
        }
    }
}

// =====================================================================
// FFMA fallback combine (round 2) — final 64-row level.
// =====================================================================
#define KS 8
#define NSTAGE 16

__global__ __launch_bounds__(256, 2) void combine2(int src_sel, float* __restrict__ out_param,
                                                   int dst_sel,
                                                   const float* __restrict__ Whh,
                                                   const float* __restrict__ bhh,
                                                   int lg_nhalf) {
    float* x_s  = smem;
    float* hl_s = x_s + 32 * 129;
    float* hr_s = hl_s + 32 * 132;
    float* w_s  = hr_s + 32 * 132;

    const float* hin = (src_sel == 0) ? g_bufA : g_bufB;
    float* hout = (dst_sel == 0) ? g_bufA : (dst_sel == 1) ? g_bufB : out_param;

    int t = threadIdx.x;
    int r0 = blockIdx.x * 32;
    int n_half = 1 << lg_nhalf;

    {
        const float4* g0 = (const float4*)(Whh);
        float* d0 = w_s;
#pragma unroll
        for (int j = 0; j < 5; j++) { int idx = t + j * 256; cp16(d0 + idx * 4, g0 + idx); }
        CP_COMMIT();
        const float4* g1 = (const float4*)(Whh + KS * 640);
        float* d1 = w_s + KS * 640;
#pragma unroll
        for (int j = 0; j < 5; j++) { int idx = t + j * 256; cp16(d1 + idx * 4, g1 + idx); }
        CP_COMMIT();
    }

    const float4* hin4 = (const float4*)hin;
    for (int i = t; i < 32 * 32; i += 256) {
        int rr = i >> 5, c4 = i & 31;
        int r = r0 + rr;
        int b = r >> lg_nhalf;
        int ii = r - (b << lg_nhalf);
        long long base = (long long)b * (2 * n_half);
        float4 l4 = hin4[(base + 2 * ii) * 32 + c4];
        float4 r4 = hin4[(base + 2 * ii + 1) * 32 + c4];
        *(float4*)&hl_s[rr * 132 + c4 * 4] = l4;
        *(float4*)&hr_s[rr * 132 + c4 * 4] = r4;
        float* xp = &x_s[rr * 129 + c4 * 4];
        xp[0] = l4.x + r4.x; xp[1] = l4.y + r4.y; xp[2] = l4.z + r4.z; xp[3] = l4.w + r4.w;
    }

    int lane = t & 31, warp = t >> 5;
    int wy = warp >> 2, wx = warp & 3;
    int rowg = lane >> 3, colg = lane & 7;
    int rbase = wy * 16 + rowg * 4;
    int cbase = wx * 32 + colg * 4;

    ull acc[4][5][2];
#pragma unroll
    for (int m = 0; m < 4; m++)
#pragma unroll
        for (int g = 0; g < 5; g++) { acc[m][g][0] = 0ULL; acc[m][g][1] = 0ULL; }

    for (int s = 0; s < NSTAGE; s++) {
        if (s == NSTAGE - 1) { CP_WAIT0(); } else { CP_WAIT1(); }
        __syncthreads();
        const float* wb = w_s + (s & 1) * KS * 640;
        int kbase = s * KS;
#pragma unroll
        for (int kk = 0; kk < KS; kk++) {
            ull ap[4];
#pragma unroll
            for (int m = 0; m < 4; m++) {
                float a = x_s[(rbase + m) * 129 + kbase + kk];
                ap[m] = pk2(a, a);
            }
#pragma unroll
            for (int g = 0; g < 5; g++) {
                float4 bv = *(const float4*)&wb[kk * 640 + g * 128 + cbase];
                ull blo = pk2(bv.x, bv.y), bhi = pk2(bv.z, bv.w);
#pragma unroll
                for (int m = 0; m < 4; m++) {
                    fma2(acc[m][g][0], ap[m], blo);
                    fma2(acc[m][g][1], ap[m], bhi);
                }
            }
        }
        __syncthreads();
        if (s + 2 < NSTAGE) {
            const float4* g4 = (const float4*)(Whh + (s + 2) * KS * 640);
            float* dst = w_s + (s & 1) * KS * 640;
#pragma unroll
            for (int j = 0; j < 5; j++) { int idx = t + j * 256; cp16(dst + idx * 4, g4 + idx); }
            CP_COMMIT();
        }
    }

    float bi[5][4];
#pragma unroll
    for (int g = 0; g < 5; g++) {
        float4 bv = *(const float4*)&bhh[g * 128 + cbase];
        bi[g][0] = 2.0f * bv.x; bi[g][1] = 2.0f * bv.y;
        bi[g][2] = 2.0f * bv.z; bi[g][3] = 2.0f * bv.w;
    }
#pragma unroll
    for (int m = 0; m < 4; m++) {
        int rr = rbase + m;
        float4 l4 = *(const float4*)&hl_s[rr * 132 + cbase];
        float4 r4 = *(const float4*)&hr_s[rr * 132 + cbase];
        float sv[5][4];
#pragma unroll
        for (int g = 0; g < 5; g++) {
            float2 lo = upk2(acc[m][g][0]), hi = upk2(acc[m][g][1]);
            sv[g][0] = lo.x + bi[g][0]; sv[g][1] = lo.y + bi[g][1];
            sv[g][2] = hi.x + bi[g][2]; sv[g][3] = hi.y + bi[g][3];
        }
        float hl4[4] = {l4.x, l4.y, l4.z, l4.w};
        float hr4[4] = {r4.x, r4.y, r4.z, r4.w};
        float ov[4];
#pragma unroll
        for (int j = 0; j < 4; j++) {
            float ig = sigf(sv[0][j]);
            float lf = sigf(sv[1][j]);
            float rf = sigf(sv[2][j]);
            float og = sigf(sv[3][j]);
            float gg = tanh_f(sv[4][j]);
            float cc = ig * gg + lf * hl4[j] + rf * hr4[j];
            ov[j] = og * tanh_f(cc);
        }
        *(float4*)&hout[(long long)(r0 + rr) * 128 + cbase] =
            make_float4(ov[0], ov[1], ov[2], ov[3]);
    }
}

// ---------------- launcher ----------------
extern "C" void kernel_launch(void* const* d_in, const int* in_sizes, int n_in,
                              void* d_out, int out_size) {
    const int* ids = (const int*)d_in[0];
    const float* emb = (const float*)d_in[1];
    const float* Wwh = (const float*)d_in[2];
    const float* Whh = (const float*)d_in[3];
    const float* bhh = (const float*)d_in[4];
    float* out = (float*)d_out;

    const int smem_embed = 98304;
    const int smem_comb2 = (32 * 129 + 2 * 32 * 132 + 2 * KS * 640) * 4;
    cudaFuncSetAttribute(embed_mma, cudaFuncAttributeMaxDynamicSharedMemorySize, smem_embed);
    cudaFuncSetAttribute(combine_pers, cudaFuncAttributeMaxDynamicSharedMemorySize, PB_SM);
    cudaFuncSetAttribute(combine2, cudaFuncAttributeMaxDynamicSharedMemorySize, smem_comb2);

    prep_w<<<(128 * 640 + 255) / 256, 256>>>(Whh);
    prep_e<<<(128 * 128 + 255) / 256, 256>>>(Wwh);
    embed_mma<<<(BB_ * LL_) / 64, 256, smem_embed>>>(ids, emb);

    for (int tlev = 1; tlev <= 11; ++tlev) {
        int n_half = LL_ >> tlev;
        int rows = BB_ * n_half;
        int lg = 11 - tlev;
        int src_sel = (tlev & 1) ? 0 : 1;
        int dst_sel = (tlev == 11) ? 2 : ((tlev & 1) ? 1 : 0);
        if (tlev <= 10) {
            int ntiles = rows / 128;
            int gx = ntiles < 74 ? ntiles : 74;
            dim3 grid(gx, 2);
            combine_pers<<<grid, 512, PB_SM>>>(src_sel, out, dst_sel, bhh, lg, ntiles);
        } else {
            combine2<<<rows / 32, 256, smem_comb2>>>(src_sel, out, dst_sel, Whh, bhh, lg);
        }
    }
}

// round 6
// speedup vs baseline: 3.4129x; 1.3918x over previous
#include <cuda_runtime.h>
#include <cuda_bf16.h>

#define BB_ 64
#define LL_ 2048

typedef unsigned long long ull;
typedef unsigned int u32;

// Ping-pong buffers for the tree levels.
__device__ float g_bufA[BB_ * LL_ * 128];        // 67 MB
__device__ float g_bufB[BB_ * (LL_ / 2) * 128];  // 33.5 MB
// Permuted split W_hh: [chunk(4)][n(160)][k(128)] bf16, n = gate*32 + within-chunk col
__device__ __align__(16) __nv_bfloat16 g_Whi[4 * 160 * 128];
__device__ __align__(16) __nv_bfloat16 g_Wlo[4 * 160 * 128];
// Split W_wh transposed: [n(128)][k(128)]
__device__ __align__(16) __nv_bfloat16 g_Ehi[128 * 128];
__device__ __align__(16) __nv_bfloat16 g_Elo[128 * 128];

extern __shared__ float smem[];

// ---------------- scalar helpers ----------------
__device__ __forceinline__ float tanhfast(float x) {
    float y; asm("tanh.approx.f32 %0, %1;" : "=f"(y) : "f"(x)); return y;
}
// sigmoid via tanh.approx: error ~2.5e-4 abs, damped as a gate multiplier.
__device__ __forceinline__ float sig_fast(float x) {
    return fmaf(0.5f, tanhfast(0.5f * x), 0.5f);
}
// exact-ish tanh (EX2 + RCP) for the value paths.
__device__ __forceinline__ float tanh_f(float x) {
    return 1.0f - 2.0f / (__expf(2.0f * x) + 1.0f);
}

// ---------------- cp.async ----------------
__device__ __forceinline__ void cp16(void* s, const void* g) {
    unsigned a = (unsigned)__cvta_generic_to_shared(s);
    asm volatile("cp.async.cg.shared.global [%0], [%1], 16;" :: "r"(a), "l"(g));
}
#define CP_COMMIT() asm volatile("cp.async.commit_group;")
#define CP_WAIT0()  asm volatile("cp.async.wait_group 0;")

// ---------------- mma.sync helpers ----------------
__device__ __forceinline__ u32 smem_u32(const void* p) {
    u32 a;
    asm("{ .reg .u64 t; cvta.to.shared.u64 t, %1; cvt.u32.u64 %0, t; }" : "=r"(a) : "l"(p));
    return a;
}
__device__ __forceinline__ void ldsm4(u32* r, u32 saddr) {
    asm volatile("ldmatrix.sync.aligned.m8n8.x4.shared.b16 {%0,%1,%2,%3}, [%4];"
                 : "=r"(r[0]), "=r"(r[1]), "=r"(r[2]), "=r"(r[3]) : "r"(saddr));
}
__device__ __forceinline__ void ldsm2(u32* r, u32 saddr) {
    asm volatile("ldmatrix.sync.aligned.m8n8.x2.shared.b16 {%0,%1}, [%2];"
                 : "=r"(r[0]), "=r"(r[1]) : "r"(saddr));
}
__device__ __forceinline__ void mma16816(float* d, const u32* a, u32 b0, u32 b1) {
    asm volatile(
        "mma.sync.aligned.m16n8k16.row.col.f32.bf16.bf16.f32 "
        "{%0,%1,%2,%3}, {%4,%5,%6,%7}, {%8,%9}, {%0,%1,%2,%3};"
        : "+f"(d[0]), "+f"(d[1]), "+f"(d[2]), "+f"(d[3])
        : "r"(a[0]), "r"(a[1]), "r"(a[2]), "r"(a[3]), "r"(b0), "r"(b1));
}

// =====================================================================
// Prep kernels: split weights to bf16 hi/lo.
// =====================================================================
__global__ void prep_w(const float* __restrict__ Whh) {
    int idx = blockIdx.x * 256 + threadIdx.x;  // over 128*640
    if (idx >= 128 * 640) return;
    int k = idx / 640, col = idx - k * 640;
    int g = col >> 7, c = col & 127;
    int chunk = c >> 5, cl = c & 31;
    int n = g * 32 + cl;
    float w = Whh[idx];
    __nv_bfloat16 hi = __float2bfloat16_rn(w);
    __nv_bfloat16 lo = __float2bfloat16_rn(w - __bfloat162float(hi));
    int dst = (chunk * 160 + n) * 128 + k;
    g_Whi[dst] = hi;
    g_Wlo[dst] = lo;
}
__global__ void prep_e(const float* __restrict__ Wwh) {
    int idx = blockIdx.x * 256 + threadIdx.x;  // over 128*128
    if (idx >= 128 * 128) return;
    int k = idx >> 7, n = idx & 127;
    float w = Wwh[idx];
    __nv_bfloat16 hi = __float2bfloat16_rn(w);
    __nv_bfloat16 lo = __float2bfloat16_rn(w - __bfloat162float(hi));
    g_Ehi[n * 128 + k] = hi;
    g_Elo[n * 128 + k] = lo;
}

// =====================================================================
// Embed via mma.sync: h0 = emb[ids] @ W_wh. CTA M=64, N=128, K=128.
// 256 thr, 8 warps (2x4), warp tile 32x32. smem 96KB -> 2 CTAs/SM.
// =====================================================================
__global__ __launch_bounds__(256, 2) void embed_mma(const int* __restrict__ ids,
                                                    const float* __restrict__ emb) {
    char* sm = (char*)smem;
    int t = threadIdx.x;
    int r0 = blockIdx.x * 64;

    for (int i = t; i < 64 * 32; i += 256) {
        int rr = i >> 5, c4 = i & 31;
        int id = ids[r0 + rr];
        float4 v = ((const float4*)emb)[(long long)id * 32 + c4];
        float xv[4] = {v.x, v.y, v.z, v.w};
        __nv_bfloat16 hi[4], lo[4];
#pragma unroll
        for (int j = 0; j < 4; j++) {
            hi[j] = __float2bfloat16_rn(xv[j]);
            lo[j] = __float2bfloat16_rn(xv[j] - __bfloat162float(hi[j]));
        }
        u32 sw = (u32)(2 * c4) ^ ((rr & 7) << 2);
        *(uint2*)(sm + (rr * 64 + sw) * 4) = *(uint2*)hi;
        *(uint2*)(sm + 16384 + (rr * 64 + sw) * 4) = *(uint2*)lo;
    }
    for (int j = t; j < 2 * 128 * 16; j += 256) {
        int split = j >> 11, rem = j & 2047;
        int row = rem >> 4, q = rem & 15;
        const __nv_bfloat16* src = split ? g_Elo : g_Ehi;
        uint4 v = *(const uint4*)&src[row * 128 + q * 8];
        u32 kpb = (u32)(4 * q) ^ ((row & 7) << 2);
        *(uint4*)(sm + 32768 + split * 32768 + (row * 64 + kpb) * 4) = v;
    }
    __syncthreads();

    u32 smb = smem_u32(sm);
    int lane = t & 31, warp = t >> 5;
    int wm = warp >> 2, wn = warp & 3;
    int t8 = lane >> 3, l7 = lane & 7;
    u32 xsw = (u32)(l7 << 2);
    int arow = wm * 32 + (t8 & 1) * 8 + l7;
    u32 tka = (u32)((t8 >> 1) * 4);
    int brow = wn * 32 + (t8 >> 1) * 8 + l7;
    u32 tkb = (u32)((t8 & 1) * 4);

    float acc[2][4][4];
#pragma unroll
    for (int a = 0; a < 2; a++)
#pragma unroll
        for (int b = 0; b < 4; b++)
#pragma unroll
            for (int c = 0; c < 4; c++) acc[a][b][c] = 0.0f;

#pragma unroll 1
    for (int ks = 0; ks < 8; ks++) {
#pragma unroll
        for (int split = 0; split < 3; split++) {
            u32 abase = smb + ((split == 2) ? 16384u : 0u);
            u32 bbase = smb + 32768u + ((split == 1) ? 32768u : 0u);
            u32 ka = (((u32)(ks * 8) + tka) ^ xsw) * 4;
            u32 kb = (((u32)(ks * 8) + tkb) ^ xsw) * 4;
            u32 af[2][4];
            ldsm4(af[0], abase + (u32)arow * 256 + ka);
            ldsm4(af[1], abase + (u32)(arow + 16) * 256 + ka);
#pragma unroll
            for (int np = 0; np < 2; np++) {
                u32 bf[4];
                ldsm4(bf, bbase + (u32)(brow + np * 16) * 256 + kb);
                mma16816(acc[0][2 * np], af[0], bf[0], bf[1]);
                mma16816(acc[0][2 * np + 1], af[0], bf[2], bf[3]);
                mma16816(acc[1][2 * np], af[1], bf[0], bf[1]);
                mma16816(acc[1][2 * np + 1], af[1], bf[2], bf[3]);
            }
        }
    }

    int grp = lane >> 2, tid4 = lane & 3;
#pragma unroll
    for (int mf = 0; mf < 2; mf++)
#pragma unroll
        for (int nf = 0; nf < 4; nf++) {
            int row = r0 + wm * 32 + mf * 16 + grp;
            int col = wn * 32 + nf * 8 + tid4 * 2;
            *(float2*)&g_bufA[(long long)row * 128 + col] =
                make_float2(acc[mf][nf][0], acc[mf][nf][1]);
            *(float2*)&g_bufA[(long long)(row + 8) * 128 + col] =
                make_float2(acc[mf][nf][2], acc[mf][nf][3]);
        }
}

// =====================================================================
// Persistent tree-level kernel, 2 CTAs/SM. Grid (<=74, 4 chunks).
// CTA = M=64 rows x N=160 (5 gates x 32 cols), 256 thr, 8 warps (2m x 4n).
// Warp wn owns cols [wn*8, wn*8+8) of every gate -> epilogue in registers.
// smem: A 2x16KB | B 2x40KB | bias 640B = 115328 B -> 2 CTAs/SM.
// =====================================================================
#define QB_ALO 16384
#define QB_B 32768
#define QB_BIAS 114688
#define QB_SM 115328

__global__ __launch_bounds__(256, 2) void combine_q(int src_sel,
                                                    float* __restrict__ out_param,
                                                    int dst_sel,
                                                    const float* __restrict__ bhh,
                                                    int lg_nhalf, int ntiles) {
    char* sm = (char*)smem;
    int t = threadIdx.x;
    int chunk = blockIdx.y;
    int n_half = 1 << lg_nhalf;

    const float* hin = (src_sel == 0) ? g_bufA : g_bufB;
    float* hout = (dst_sel == 0) ? g_bufA : (dst_sel == 1) ? g_bufB : out_param;

    // B fill once via cp.async: [split(2)][row 160][16 uint4], swizzled.
    for (int j = t; j < 2 * 160 * 16; j += 256) {
        int split = j / 2560, rem = j - split * 2560;
        int row = rem >> 4, q = rem & 15;
        const __nv_bfloat16* src = split ? g_Wlo : g_Whi;
        u32 kpb = (u32)(4 * q) ^ ((row & 7) << 2);
        cp16(sm + QB_B + split * 40960 + (row * 64 + kpb) * 4,
             &src[(chunk * 160 + row) * 128 + q * 8]);
    }
    CP_COMMIT();
    // Chunk-local bias (pre-doubled): [g*32 + cl]
    float* bias_s = (float*)(sm + QB_BIAS);
    for (int j = t; j < 160; j += 256)
        bias_s[j] = 2.0f * bhh[(j >> 5) * 128 + chunk * 32 + (j & 31)];

    u32 smb = smem_u32(sm);
    int lane = t & 31, warp = t >> 5;
    int wm = warp >> 2, wn = warp & 3;  // 2 x 4
    int t8 = lane >> 3, l7 = lane & 7;
    u32 xsw = (u32)(l7 << 2);
    int arow = wm * 32 + (t8 & 1) * 8 + l7;
    u32 tka = (u32)((t8 >> 1) * 4);
    int rowB = wn * 8 + l7;             // row within a gate's 32
    int bgsel = t8 >> 1;                // which gate of the x4 pair
    u32 tkb = (u32)((t8 & 1) * 4);
    int grp = lane >> 2, tid4 = lane & 3;

    const float4* hin4 = (const float4*)hin;

    for (int tile = blockIdx.x; tile < ntiles; tile += gridDim.x) {
        int r0 = tile * 64;
        __syncthreads();  // previous tile's MMA done before A overwrite; bias ready

        // A fill: x = hl + hr, split bf16 hi/lo, swizzled.
        for (int i = t; i < 64 * 32; i += 256) {
            int rr = i >> 5, c4 = i & 31;
            int r = r0 + rr;
            int b = r >> lg_nhalf;
            int ii = r - (b << lg_nhalf);
            long long base = (long long)b * (2 * n_half);
            float4 l4 = hin4[(base + 2 * ii) * 32 + c4];
            float4 r4 = hin4[(base + 2 * ii + 1) * 32 + c4];
            float xv[4] = {l4.x + r4.x, l4.y + r4.y, l4.z + r4.z, l4.w + r4.w};
            __nv_bfloat16 hi[4], lo[4];
#pragma unroll
            for (int j = 0; j < 4; j++) {
                hi[j] = __float2bfloat16_rn(xv[j]);
                lo[j] = __float2bfloat16_rn(xv[j] - __bfloat162float(hi[j]));
            }
            u32 sw = (u32)(2 * c4) ^ ((rr & 7) << 2);
            *(uint2*)(sm + (rr * 64 + sw) * 4) = *(uint2*)hi;
            *(uint2*)(sm + QB_ALO + (rr * 64 + sw) * 4) = *(uint2*)lo;
        }
        CP_WAIT0();  // B ready (no-op after first tile)
        __syncthreads();

        // MMA: acc[mf(2)][gate(5)][4]
        float acc[2][5][4];
#pragma unroll
        for (int a = 0; a < 2; a++)
#pragma unroll
            for (int g = 0; g < 5; g++)
#pragma unroll
                for (int c = 0; c < 4; c++) acc[a][g][c] = 0.0f;

#pragma unroll 1
        for (int ks = 0; ks < 8; ks++) {
#pragma unroll
            for (int split = 0; split < 3; split++) {
                u32 abase = smb + ((split == 2) ? (u32)QB_ALO : 0u);
                u32 bbase = smb + QB_B + ((split == 1) ? 40960u : 0u);
                u32 ka = (((u32)(ks * 8) + tka) ^ xsw) * 4;
                u32 kb = (((u32)(ks * 8) + tkb) ^ xsw) * 4;
                u32 af[2][4];
                ldsm4(af[0], abase + (u32)arow * 256 + ka);
                ldsm4(af[1], abase + (u32)(arow + 16) * 256 + ka);
                u32 b01[4], b23[4], b4[2];
                ldsm4(b01, bbase + (u32)((0 + bgsel) * 32 + rowB) * 256 + kb);
                ldsm4(b23, bbase + (u32)((2 + bgsel) * 32 + rowB) * 256 + kb);
                ldsm2(b4, bbase + (u32)(4 * 32 + rowB) * 256 + kb);
                mma16816(acc[0][0], af[0], b01[0], b01[1]);
                mma16816(acc[1][0], af[1], b01[0], b01[1]);
                mma16816(acc[0][1], af[0], b01[2], b01[3]);
                mma16816(acc[1][1], af[1], b01[2], b01[3]);
                mma16816(acc[0][2], af[0], b23[0], b23[1]);
                mma16816(acc[1][2], af[1], b23[0], b23[1]);
                mma16816(acc[0][3], af[0], b23[2], b23[3]);
                mma16816(acc[1][3], af[1], b23[2], b23[3]);
                mma16816(acc[0][4], af[0], b4[0], b4[1]);
                mma16816(acc[1][4], af[1], b4[0], b4[1]);
            }
        }

        // Epilogue: all 5 gates in registers. 4 rows x 2 cols per thread.
        int cl = wn * 8 + tid4 * 2;
        int hcol = chunk * 32 + cl;
#pragma unroll
        for (int mf = 0; mf < 2; mf++) {
#pragma unroll
            for (int half = 0; half < 2; half++) {
                int rr = wm * 32 + mf * 16 + grp + half * 8;
                int r = r0 + rr;
                int b = r >> lg_nhalf;
                int ii = r - (b << lg_nhalf);
                long long rowL = (long long)b * (2 * n_half) + 2 * ii;
                float2 hlv = *(const float2*)&hin[rowL * 128 + hcol];
                float2 hrv = *(const float2*)&hin[(rowL + 1) * 128 + hcol];
                float hl2[2] = {hlv.x, hlv.y};
                float hr2[2] = {hrv.x, hrv.y};
                float ov[2];
#pragma unroll
                for (int j = 0; j < 2; j++) {
                    int e = half * 2 + j;
                    float si = acc[mf][0][e] + bias_s[0 * 32 + cl + j];
                    float sl = acc[mf][1][e] + bias_s[1 * 32 + cl + j];
                    float sr = acc[mf][2][e] + bias_s[2 * 32 + cl + j];
                    float so = acc[mf][3][e] + bias_s[3 * 32 + cl + j];
                    float sg = acc[mf][4][e] + bias_s[4 * 32 + cl + j];
                    float cc = sig_fast(si) * tanh_f(sg) + sig_fast(sl) * hl2[j] +
                               sig_fast(sr) * hr2[j];
                    ov[j] = sig_fast(so) * tanh_f(cc);
                }
                *(float2*)&hout[(long long)r * 128 + hcol] = make_float2(ov[0], ov[1]);
            }
        }
    }
}

// ---------------- launcher ----------------
extern "C" void kernel_launch(void* const* d_in, const int* in_sizes, int n_in,
                              void* d_out, int out_size) {
    const int* ids = (const int*)d_in[0];
    const float* emb = (const float*)d_in[1];
    const float* Wwh = (const float*)d_in[2];
    const float* Whh = (const float*)d_in[3];
    const float* bhh = (const float*)d_in[4];
    float* out = (float*)d_out;

    const int smem_embed = 98304;
    cudaFuncSetAttribute(embed_mma, cudaFuncAttributeMaxDynamicSharedMemorySize, smem_embed);
    cudaFuncSetAttribute(combine_q, cudaFuncAttributeMaxDynamicSharedMemorySize, QB_SM);

    prep_w<<<(128 * 640 + 255) / 256, 256>>>(Whh);
    prep_e<<<(128 * 128 + 255) / 256, 256>>>(Wwh);
    embed_mma<<<(BB_ * LL_) / 64, 256, smem_embed>>>(ids, emb);

    for (int tlev = 1; tlev <= 11; ++tlev) {
        int ntiles = (BB_ * (LL_ >> tlev)) / 64;  // M=64 tiles
        int lg = 11 - tlev;
        int src_sel = (tlev & 1) ? 0 : 1;
        int dst_sel = (tlev == 11) ? 2 : ((tlev & 1) ? 1 : 0);
        int gx = ntiles < 74 ? ntiles : 74;
        dim3 grid(gx, 4);
        combine_q<<<grid, 256, QB_SM>>>(src_sel, out, dst_sel, bhh, lg, ntiles);
    }
}

// round 7
// speedup vs baseline: 3.8677x; 1.1333x over previous
#include <cuda_runtime.h>
#include <cuda_bf16.h>

#define BB_ 64
#define LL_ 2048

typedef unsigned long long ull;
typedef unsigned int u32;

// Ping-pong buffers for the tree levels.
__device__ float g_bufA[BB_ * LL_ * 128];        // 67 MB
__device__ float g_bufB[BB_ * (LL_ / 2) * 128];  // 33.5 MB
// Permuted split W_hh: [chunk(4)][n(160)][k(128)] bf16, n = gate*32 + within-chunk col
__device__ __align__(16) __nv_bfloat16 g_Whi[4 * 160 * 128];
__device__ __align__(16) __nv_bfloat16 g_Wlo[4 * 160 * 128];
// Split W_wh transposed: [n(128)][k(128)]
__device__ __align__(16) __nv_bfloat16 g_Ehi[128 * 128];
__device__ __align__(16) __nv_bfloat16 g_Elo[128 * 128];

extern __shared__ float smem[];

// ---------------- scalar helpers ----------------
__device__ __forceinline__ float tanhfast(float x) {
    float y; asm("tanh.approx.f32 %0, %1;" : "=f"(y) : "f"(x)); return y;
}
__device__ __forceinline__ float sig_fast(float x) {
    return fmaf(0.5f, tanhfast(0.5f * x), 0.5f);
}
__device__ __forceinline__ float tanh_f(float x) {
    return 1.0f - 2.0f / (__expf(2.0f * x) + 1.0f);
}

// ---------------- cp.async ----------------
__device__ __forceinline__ void cp16(void* s, const void* g) {
    unsigned a = (unsigned)__cvta_generic_to_shared(s);
    asm volatile("cp.async.cg.shared.global [%0], [%1], 16;" :: "r"(a), "l"(g));
}
#define CP_COMMIT() asm volatile("cp.async.commit_group;")
#define CP_WAIT0()  asm volatile("cp.async.wait_group 0;")

// ---------------- mma.sync helpers ----------------
__device__ __forceinline__ u32 smem_u32(const void* p) {
    u32 a;
    asm("{ .reg .u64 t; cvta.to.shared.u64 t, %1; cvt.u32.u64 %0, t; }" : "=r"(a) : "l"(p));
    return a;
}
__device__ __forceinline__ void ldsm4(u32* r, u32 saddr) {
    asm volatile("ldmatrix.sync.aligned.m8n8.x4.shared.b16 {%0,%1,%2,%3}, [%4];"
                 : "=r"(r[0]), "=r"(r[1]), "=r"(r[2]), "=r"(r[3]) : "r"(saddr));
}
__device__ __forceinline__ void ldsm2(u32* r, u32 saddr) {
    asm volatile("ldmatrix.sync.aligned.m8n8.x2.shared.b16 {%0,%1}, [%2];"
                 : "=r"(r[0]), "=r"(r[1]) : "r"(saddr));
}
__device__ __forceinline__ void mma16816(float* d, const u32* a, u32 b0, u32 b1) {
    asm volatile(
        "mma.sync.aligned.m16n8k16.row.col.f32.bf16.bf16.f32 "
        "{%0,%1,%2,%3}, {%4,%5,%6,%7}, {%8,%9}, {%0,%1,%2,%3};"
        : "+f"(d[0]), "+f"(d[1]), "+f"(d[2]), "+f"(d[3])
        : "r"(a[0]), "r"(a[1]), "r"(a[2]), "r"(a[3]), "r"(b0), "r"(b1));
}

// =====================================================================
// Prep kernels: split weights to bf16 hi/lo.
// =====================================================================
__global__ void prep_w(const float* __restrict__ Whh) {
    int idx = blockIdx.x * 256 + threadIdx.x;  // over 128*640
    if (idx >= 128 * 640) return;
    int k = idx / 640, col = idx - k * 640;
    int g = col >> 7, c = col & 127;
    int chunk = c >> 5, cl = c & 31;
    int n = g * 32 + cl;
    float w = Whh[idx];
    __nv_bfloat16 hi = __float2bfloat16_rn(w);
    __nv_bfloat16 lo = __float2bfloat16_rn(w - __bfloat162float(hi));
    int dst = (chunk * 160 + n) * 128 + k;
    g_Whi[dst] = hi;
    g_Wlo[dst] = lo;
}
__global__ void prep_e(const float* __restrict__ Wwh) {
    int idx = blockIdx.x * 256 + threadIdx.x;  // over 128*128
    if (idx >= 128 * 128) return;
    int k = idx >> 7, n = idx & 127;
    float w = Wwh[idx];
    __nv_bfloat16 hi = __float2bfloat16_rn(w);
    __nv_bfloat16 lo = __float2bfloat16_rn(w - __bfloat162float(hi));
    g_Ehi[n * 128 + k] = hi;
    g_Elo[n * 128 + k] = lo;
}

// =====================================================================
// PERSISTENT embed: h0 = emb[ids] @ W_wh. W-split resident in smem,
// CTA loops over M=64 gather tiles. 256 thr, 8 warps (2x4), warp 32x32.
// smem: Ahi 16K | Alo 16K | Bhi 32K | Blo 32K = 96KB -> 2 CTAs/SM.
// =====================================================================
__global__ __launch_bounds__(256, 2) void embed_pers(const int* __restrict__ ids,
                                                     const float* __restrict__ emb,
                                                     int ntiles) {
    char* sm = (char*)smem;
    int t = threadIdx.x;

    // B fill once via cp.async.
    for (int j = t; j < 2 * 128 * 16; j += 256) {
        int split = j >> 11, rem = j & 2047;
        int row = rem >> 4, q = rem & 15;
        const __nv_bfloat16* src = split ? g_Elo : g_Ehi;
        u32 kpb = (u32)(4 * q) ^ ((row & 7) << 2);
        cp16(sm + 32768 + split * 32768 + (row * 64 + kpb) * 4, &src[row * 128 + q * 8]);
    }
    CP_COMMIT();

    u32 smb = smem_u32(sm);
    int lane = t & 31, warp = t >> 5;
    int wm = warp >> 2, wn = warp & 3;
    int t8 = lane >> 3, l7 = lane & 7;
    u32 xsw = (u32)(l7 << 2);
    int arow = wm * 32 + (t8 & 1) * 8 + l7;
    u32 tka = (u32)((t8 >> 1) * 4);
    int brow = wn * 32 + (t8 >> 1) * 8 + l7;
    u32 tkb = (u32)((t8 & 1) * 4);
    int grp = lane >> 2, tid4 = lane & 3;

    for (int tile = blockIdx.x; tile < ntiles; tile += gridDim.x) {
        int r0 = tile * 64;
        __syncthreads();  // previous tile MMA done before A overwrite

        // A: gather + split.
        for (int i = t; i < 64 * 32; i += 256) {
            int rr = i >> 5, c4 = i & 31;
            int id = ids[r0 + rr];
            float4 v = ((const float4*)emb)[(long long)id * 32 + c4];
            float xv[4] = {v.x, v.y, v.z, v.w};
            __nv_bfloat16 hi[4], lo[4];
#pragma unroll
            for (int j = 0; j < 4; j++) {
                hi[j] = __float2bfloat16_rn(xv[j]);
                lo[j] = __float2bfloat16_rn(xv[j] - __bfloat162float(hi[j]));
            }
            u32 sw = (u32)(2 * c4) ^ ((rr & 7) << 2);
            *(uint2*)(sm + (rr * 64 + sw) * 4) = *(uint2*)hi;
            *(uint2*)(sm + 16384 + (rr * 64 + sw) * 4) = *(uint2*)lo;
        }
        CP_WAIT0();  // B ready (no-op after first tile)
        __syncthreads();

        float acc[2][4][4];
#pragma unroll
        for (int a = 0; a < 2; a++)
#pragma unroll
            for (int b = 0; b < 4; b++)
#pragma unroll
                for (int c = 0; c < 4; c++) acc[a][b][c] = 0.0f;

#pragma unroll 1
        for (int ks = 0; ks < 8; ks++) {
#pragma unroll
            for (int split = 0; split < 3; split++) {
                u32 abase = smb + ((split == 2) ? 16384u : 0u);
                u32 bbase = smb + 32768u + ((split == 1) ? 32768u : 0u);
                u32 ka = (((u32)(ks * 8) + tka) ^ xsw) * 4;
                u32 kb = (((u32)(ks * 8) + tkb) ^ xsw) * 4;
                u32 af[2][4];
                ldsm4(af[0], abase + (u32)arow * 256 + ka);
                ldsm4(af[1], abase + (u32)(arow + 16) * 256 + ka);
#pragma unroll
                for (int np = 0; np < 2; np++) {
                    u32 bf[4];
                    ldsm4(bf, bbase + (u32)(brow + np * 16) * 256 + kb);
                    mma16816(acc[0][2 * np], af[0], bf[0], bf[1]);
                    mma16816(acc[0][2 * np + 1], af[0], bf[2], bf[3]);
                    mma16816(acc[1][2 * np], af[1], bf[0], bf[1]);
                    mma16816(acc[1][2 * np + 1], af[1], bf[2], bf[3]);
                }
            }
        }

#pragma unroll
        for (int mf = 0; mf < 2; mf++)
#pragma unroll
            for (int nf = 0; nf < 4; nf++) {
                int row = r0 + wm * 32 + mf * 16 + grp;
                int col = wn * 32 + nf * 8 + tid4 * 2;
                *(float2*)&g_bufA[(long long)row * 128 + col] =
                    make_float2(acc[mf][nf][0], acc[mf][nf][1]);
                *(float2*)&g_bufA[(long long)(row + 8) * 128 + col] =
                    make_float2(acc[mf][nf][2], acc[mf][nf][3]);
            }
    }
}

// =====================================================================
// Persistent tree-level kernel, 2 CTAs/SM. Grid (<=74, 4 chunks).
// CTA = M=64 rows x N=160 (5 gates x 32 cols), 256 thr, 8 warps (2m x 4n).
// Epilogue hl/hr prefetched into registers before the MMA loop.
// smem: A 2x16KB | B 2x40KB | bias 640B = 115328 B -> 2 CTAs/SM.
// =====================================================================
#define QB_ALO 16384
#define QB_B 32768
#define QB_BIAS 114688
#define QB_SM 115328

__global__ __launch_bounds__(256, 2) void combine_q(int src_sel,
                                                    float* __restrict__ out_param,
                                                    int dst_sel,
                                                    const float* __restrict__ bhh,
                                                    int lg_nhalf, int ntiles) {
    char* sm = (char*)smem;
    int t = threadIdx.x;
    int chunk = blockIdx.y;
    int n_half = 1 << lg_nhalf;

    const float* hin = (src_sel == 0) ? g_bufA : g_bufB;
    float* hout = (dst_sel == 0) ? g_bufA : (dst_sel == 1) ? g_bufB : out_param;

    // B fill once via cp.async: [split(2)][row 160][16 uint4], swizzled.
    for (int j = t; j < 2 * 160 * 16; j += 256) {
        int split = j / 2560, rem = j - split * 2560;
        int row = rem >> 4, q = rem & 15;
        const __nv_bfloat16* src = split ? g_Wlo : g_Whi;
        u32 kpb = (u32)(4 * q) ^ ((row & 7) << 2);
        cp16(sm + QB_B + split * 40960 + (row * 64 + kpb) * 4,
             &src[(chunk * 160 + row) * 128 + q * 8]);
    }
    CP_COMMIT();
    float* bias_s = (float*)(sm + QB_BIAS);
    for (int j = t; j < 160; j += 256)
        bias_s[j] = 2.0f * bhh[(j >> 5) * 128 + chunk * 32 + (j & 31)];

    u32 smb = smem_u32(sm);
    int lane = t & 31, warp = t >> 5;
    int wm = warp >> 2, wn = warp & 3;  // 2 x 4
    int t8 = lane >> 3, l7 = lane & 7;
    u32 xsw = (u32)(l7 << 2);
    int arow = wm * 32 + (t8 & 1) * 8 + l7;
    u32 tka = (u32)((t8 >> 1) * 4);
    int rowB = wn * 8 + l7;
    int bgsel = t8 >> 1;
    u32 tkb = (u32)((t8 & 1) * 4);
    int grp = lane >> 2, tid4 = lane & 3;
    int cl = wn * 8 + tid4 * 2;
    int hcol = chunk * 32 + cl;

    const float4* hin4 = (const float4*)hin;

    for (int tile = blockIdx.x; tile < ntiles; tile += gridDim.x) {
        int r0 = tile * 64;
        __syncthreads();  // previous tile's MMA done before A overwrite

        // A fill: x = hl + hr, split bf16 hi/lo, swizzled.
        for (int i = t; i < 64 * 32; i += 256) {
            int rr = i >> 5, c4 = i & 31;
            int r = r0 + rr;
            int b = r >> lg_nhalf;
            int ii = r - (b << lg_nhalf);
            long long base = (long long)b * (2 * n_half);
            float4 l4 = hin4[(base + 2 * ii) * 32 + c4];
            float4 r4 = hin4[(base + 2 * ii + 1) * 32 + c4];
            float xv[4] = {l4.x + r4.x, l4.y + r4.y, l4.z + r4.z, l4.w + r4.w};
            __nv_bfloat16 hi[4], lo[4];
#pragma unroll
            for (int j = 0; j < 4; j++) {
                hi[j] = __float2bfloat16_rn(xv[j]);
                lo[j] = __float2bfloat16_rn(xv[j] - __bfloat162float(hi[j]));
            }
            u32 sw = (u32)(2 * c4) ^ ((rr & 7) << 2);
            *(uint2*)(sm + (rr * 64 + sw) * 4) = *(uint2*)hi;
            *(uint2*)(sm + QB_ALO + (rr * 64 + sw) * 4) = *(uint2*)lo;
        }

        // Prefetch epilogue operands (latency drains behind the MMA loop).
        float2 hl_pre[2][2], hr_pre[2][2];
#pragma unroll
        for (int mf = 0; mf < 2; mf++)
#pragma unroll
            for (int half = 0; half < 2; half++) {
                int rr = wm * 32 + mf * 16 + grp + half * 8;
                int r = r0 + rr;
                int b = r >> lg_nhalf;
                int ii = r - (b << lg_nhalf);
                long long rowL = (long long)b * (2 * n_half) + 2 * ii;
                hl_pre[mf][half] = *(const float2*)&hin[rowL * 128 + hcol];
                hr_pre[mf][half] = *(const float2*)&hin[(rowL + 1) * 128 + hcol];
            }

        CP_WAIT0();  // B ready (no-op after first tile)
        __syncthreads();

        float acc[2][5][4];
#pragma unroll
        for (int a = 0; a < 2; a++)
#pragma unroll
            for (int g = 0; g < 5; g++)
#pragma unroll
                for (int c = 0; c < 4; c++) acc[a][g][c] = 0.0f;

#pragma unroll 1
        for (int ks = 0; ks < 8; ks++) {
#pragma unroll
            for (int split = 0; split < 3; split++) {
                u32 abase = smb + ((split == 2) ? (u32)QB_ALO : 0u);
                u32 bbase = smb + QB_B + ((split == 1) ? 40960u : 0u);
                u32 ka = (((u32)(ks * 8) + tka) ^ xsw) * 4;
                u32 kb = (((u32)(ks * 8) + tkb) ^ xsw) * 4;
                u32 af[2][4];
                ldsm4(af[0], abase + (u32)arow * 256 + ka);
                ldsm4(af[1], abase + (u32)(arow + 16) * 256 + ka);
                u32 b01[4], b23[4], b4[2];
                ldsm4(b01, bbase + (u32)((0 + bgsel) * 32 + rowB) * 256 + kb);
                ldsm4(b23, bbase + (u32)((2 + bgsel) * 32 + rowB) * 256 + kb);
                ldsm2(b4, bbase + (u32)(4 * 32 + rowB) * 256 + kb);
                mma16816(acc[0][0], af[0], b01[0], b01[1]);
                mma16816(acc[1][0], af[1], b01[0], b01[1]);
                mma16816(acc[0][1], af[0], b01[2], b01[3]);
                mma16816(acc[1][1], af[1], b01[2], b01[3]);
                mma16816(acc[0][2], af[0], b23[0], b23[1]);
                mma16816(acc[1][2], af[1], b23[0], b23[1]);
                mma16816(acc[0][3], af[0], b23[2], b23[3]);
                mma16816(acc[1][3], af[1], b23[2], b23[3]);
                mma16816(acc[0][4], af[0], b4[0], b4[1]);
                mma16816(acc[1][4], af[1], b4[0], b4[1]);
            }
        }

        // Epilogue: gates + hl/hr already in registers.
#pragma unroll
        for (int mf = 0; mf < 2; mf++) {
#pragma unroll
            for (int half = 0; half < 2; half++) {
                int rr = wm * 32 + mf * 16 + grp + half * 8;
                int r = r0 + rr;
                float hl2[2] = {hl_pre[mf][half].x, hl_pre[mf][half].y};
                float hr2[2] = {hr_pre[mf][half].x, hr_pre[mf][half].y};
                float ov[2];
#pragma unroll
                for (int j = 0; j < 2; j++) {
                    int e = half * 2 + j;
                    float si = acc[mf][0][e] + bias_s[0 * 32 + cl + j];
                    float sl = acc[mf][1][e] + bias_s[1 * 32 + cl + j];
                    float sr = acc[mf][2][e] + bias_s[2 * 32 + cl + j];
                    float so = acc[mf][3][e] + bias_s[3 * 32 + cl + j];
                    float sg = acc[mf][4][e] + bias_s[4 * 32 + cl + j];
                    float cc = sig_fast(si) * tanh_f(sg) + sig_fast(sl) * hl2[j] +
                               sig_fast(sr) * hr2[j];
                    ov[j] = sig_fast(so) * tanh_f(cc);
                }
                *(float2*)&hout[(long long)r * 128 + hcol] = make_float2(ov[0], ov[1]);
            }
        }
    }
}

// ---------------- launcher ----------------
extern "C" void kernel_launch(void* const* d_in, const int* in_sizes, int n_in,
                              void* d_out, int out_size) {
    const int* ids = (const int*)d_in[0];
    const float* emb = (const float*)d_in[1];
    const float* Wwh = (const float*)d_in[2];
    const float* Whh = (const float*)d_in[3];
    const float* bhh = (const float*)d_in[4];
    float* out = (float*)d_out;

    const int smem_embed = 98304;
    cudaFuncSetAttribute(embed_pers, cudaFuncAttributeMaxDynamicSharedMemorySize, smem_embed);
    cudaFuncSetAttribute(combine_q, cudaFuncAttributeMaxDynamicSharedMemorySize, QB_SM);

    prep_w<<<(128 * 640 + 255) / 256, 256>>>(Whh);
    prep_e<<<(128 * 128 + 255) / 256, 256>>>(Wwh);

    {
        int ntiles = (BB_ * LL_) / 64;  // 2048
        int gx = ntiles < 296 ? ntiles : 296;
        embed_pers<<<gx, 256, smem_embed>>>(ids, emb, ntiles);
    }

    for (int tlev = 1; tlev <= 11; ++tlev) {
        int ntiles = (BB_ * (LL_ >> tlev)) / 64;  // M=64 tiles
        int lg = 11 - tlev;
        int src_sel = (tlev & 1) ? 0 : 1;
        int dst_sel = (tlev == 11) ? 2 : ((tlev & 1) ? 1 : 0);
        int gx = ntiles < 74 ? ntiles : 74;
        dim3 grid(gx, 4);
        combine_q<<<grid, 256, QB_SM>>>(src_sel, out, dst_sel, bhh, lg, ntiles);
    }
}